// round 13
// baseline (speedup 1.0000x reference)
#include <cuda_runtime.h>
#include <cuda_bf16.h>
#include <math.h>
#include <stdint.h>

#define BB 8
#define NN 4096
#define DEG 16
#define UU 128
#define EE (NN*DEG)
#define MM (BB*NN)
#define K2 256
#define DEPTH 3
#define SCALE_C 1.2304489f
#define THREADS 576
#define TILE_M 32
#define NTILES (MM/TILE_M)
#define GRIDSZ 148

// ------------------- device scratch (ping-pong feature buffers) -------------------
__device__ float g_xa[(size_t)MM * UU];
__device__ float g_xb[(size_t)MM * UU];
__device__ __nv_bfloat16 g_bhi[DEPTH * UU * K2];       // folded W, [n][k] K-major, hi
__device__ __nv_bfloat16 g_blo[DEPTH * UU * K2];
__device__ float g_bn_a[DEPTH * UU];
__device__ float g_bn_d[DEPTH * UU];
__device__ float g_gm[BB * UU];

// ------------------- helpers -------------------
__device__ __forceinline__ uint32_t smem_u32(const void* p) {
    uint32_t a;
    asm("{ .reg .u64 t; cvta.to.shared.u64 t, %1; cvt.u32.u64 %0, t; }" : "=r"(a) : "l"(p));
    return a;
}
__device__ __forceinline__ void cp16(uint32_t dst, const void* src) {
    asm volatile("cp.async.cg.shared.global [%0], [%1], 16;" :: "r"(dst), "l"(src) : "memory");
}
__device__ __forceinline__ void ldmx4(uint32_t* r, uint32_t addr) {
    asm volatile("ldmatrix.sync.aligned.m8n8.x4.shared.b16 {%0,%1,%2,%3}, [%4];"
                 : "=r"(r[0]), "=r"(r[1]), "=r"(r[2]), "=r"(r[3]) : "r"(addr));
}
__device__ __forceinline__ void mma_bf16(float* c, const uint32_t* a, uint32_t b0, uint32_t b1) {
    asm volatile("mma.sync.aligned.m16n8k16.row.col.f32.bf16.bf16.f32 "
                 "{%0,%1,%2,%3}, {%4,%5,%6,%7}, {%8,%9}, {%0,%1,%2,%3};"
                 : "+f"(c[0]), "+f"(c[1]), "+f"(c[2]), "+f"(c[3])
                 : "r"(a[0]), "r"(a[1]), "r"(a[2]), "r"(a[3]), "r"(b0), "r"(b1));
}
#define SWZ(off) ((off) ^ (((off) >> 3) & 0x70))
#define BAR_SYNC(id, cnt)   asm volatile("bar.sync %0, %1;"   :: "r"(id), "r"(cnt) : "memory")
#define BAR_ARRIVE(id, cnt) asm volatile("bar.arrive %0, %1;" :: "r"(id), "r"(cnt) : "memory")

// ------------------- prep: weight folding + BN fold + g_gm zero (one kernel) -------------------
__global__ void prep_kernel(const float* __restrict__ W,
                            const float* __restrict__ gamma, const float* __restrict__ beta,
                            const float* __restrict__ mm, const float* __restrict__ mv) {
    int t = blockIdx.x * blockDim.x + threadIdx.x;
    if (t < BB * UU) g_gm[t] = 0.f;
    if (t < DEPTH * UU) {
        float a = gamma[t] * rsqrtf(mv[t] + 1e-3f);
        g_bn_a[t] = a;
        g_bn_d[t] = beta[t] - mm[t] * a;
    }
    if (t >= DEPTH * K2 * UU) return;
    int j = t & 127;          // output feature n
    int k = (t >> 7) & 255;   // k index
    int l = t >> 15;
    const float c = SCALE_C;
    const float* Wl = W + (size_t)l * 1152 * UU;
    float v;
    if (k < 128) {
        float w0 = Wl[(0 * 128 + k) * UU + j];
        float w1 = Wl[(1 * 128 + k) * UU + j];
        float w2 = Wl[(2 * 128 + k) * UU + j];
        float w6 = Wl[(6 * 128 + k) * UU + j];
        float w7 = Wl[(7 * 128 + k) * UU + j];
        float w8 = Wl[(8 * 128 + k) * UU + j];
        v = (w0 + c * (w1 + w2)) * 0.0625f + w6 + c * (w7 + w8);
    } else {
        int kk = k - 128;
        float w3 = Wl[(3 * 128 + kk) * UU + j];
        float w4 = Wl[(4 * 128 + kk) * UU + j];
        float w5 = Wl[(5 * 128 + kk) * UU + j];
        v = w3 + c * (w4 + w5);
    }
    __nv_bfloat16 hi = __float2bfloat16_rn(v);
    size_t o = (size_t)l * UU * K2 + (size_t)j * K2 + k;
    g_bhi[o] = hi;
    g_blo[o] = __float2bfloat16_rn(v - __bfloat162float(hi));
}

// ------------------- warp-specialized fused layer kernel -------------------
// 576 threads: warps 0-15 produce (gather->A smem, 2 nodes each, depth-4 prefetch),
// warps 16-17 consume (MMA M=32 full x N=64 slice each + epilogue).
// Tile M=32, N=128, K=256. A double-buffered (2x32KB), B resident (128KB).
#define SB_HI   0
#define SB_LO   65536
#define SA_BASE 131072
#define SA_BUFSZ 32768
#define S_EPI   (131072 + 2*SA_BUFSZ)
#define FUSED_SMEM (S_EPI + 3*128*4)
// named barriers: full[buf]=1+buf, empty[buf]=3+buf, consumer-init=5

__global__ __launch_bounds__(THREADS, 1) void fused_layer_kernel(
        int l, const float* __restrict__ xin, float* __restrict__ xout,
        const int* __restrict__ ei, const float* __restrict__ bias,
        int fuse_readout) {
    extern __shared__ __align__(1024) char smem[];
    uint32_t sb = smem_u32(smem);
    int tid = threadIdx.x, lane = tid & 31, wid = tid >> 5;

    if (wid < 16) {
        // ===================== PRODUCER (16 warps, 2 nodes each, depth-4 prefetch) =====================
        const float ninf = __int_as_float(0xff800000);
        uint32_t csum = (uint32_t)(lane >> 4) * 4096;       // ssum chunk (0 or 1)
        uint32_t cmax = csum + 2 * 4096;                    // smax chunk (2 or 3)
        uint32_t cb   = (uint32_t)(lane & 15) * 8;
        int r0 = wid * 2;                                    // 2 nodes per warp

        int it = 0;
        for (int tile = blockIdx.x; tile < NTILES; tile += GRIDSZ, it++) {
            int buf = it & 1;
            if (it >= 2) BAR_SYNC(3 + buf, THREADS);
            uint32_t abase_hi = sb + SA_BASE + buf * SA_BUFSZ;
            uint32_t abase_lo = abase_hi + 16384;

            int node0 = tile * TILE_M;
            int b = node0 >> 12;
            int nd0 = node0 & (NN - 1);
            const float* xb = xin + (size_t)b * NN * UU;
            const int* ep = ei + 2 * ((size_t)b * EE + (size_t)(nd0 + r0) * DEG);

            int myd0 = (lane < DEG) ? ep[2 * lane + 1] : 0;
            int myd1 = (lane < DEG) ? ep[2 * DEG + 2 * lane + 1] : 0;

            float4 s0 = make_float4(0.f, 0.f, 0.f, 0.f);
            float4 s1 = make_float4(0.f, 0.f, 0.f, 0.f);
            float4 m0 = make_float4(ninf, ninf, ninf, ninf);
            float4 m1 = make_float4(ninf, ninf, ninf, ninf);

            // depth-4 software prefetch (8 x 512B in flight per warp)
            float4 pf[4][2];
            #pragma unroll
            for (int pe = 0; pe < 4; pe++) {
                int d0 = __shfl_sync(0xffffffffu, myd0, pe);
                int d1 = __shfl_sync(0xffffffffu, myd1, pe);
                pf[pe][0] = __ldg((const float4*)(xb + (size_t)d0 * UU + lane * 4));
                pf[pe][1] = __ldg((const float4*)(xb + (size_t)d1 * UU + lane * 4));
            }
            #pragma unroll
            for (int e = 0; e < DEG; e++) {
                int slot = e & 3;
                float4 v0 = pf[slot][0];
                float4 v1 = pf[slot][1];
                if (e + 4 < DEG) {
                    int d0 = __shfl_sync(0xffffffffu, myd0, e + 4);
                    int d1 = __shfl_sync(0xffffffffu, myd1, e + 4);
                    pf[slot][0] = __ldg((const float4*)(xb + (size_t)d0 * UU + lane * 4));
                    pf[slot][1] = __ldg((const float4*)(xb + (size_t)d1 * UU + lane * 4));
                }
                s0.x += v0.x; s0.y += v0.y; s0.z += v0.z; s0.w += v0.w;
                m0.x = fmaxf(m0.x, v0.x); m0.y = fmaxf(m0.y, v0.y);
                m0.z = fmaxf(m0.z, v0.z); m0.w = fmaxf(m0.w, v0.w);
                s1.x += v1.x; s1.y += v1.y; s1.z += v1.z; s1.w += v1.w;
                m1.x = fmaxf(m1.x, v1.x); m1.y = fmaxf(m1.y, v1.y);
                m1.z = fmaxf(m1.z, v1.z); m1.w = fmaxf(m1.w, v1.w);
            }

            #pragma unroll
            for (int n2 = 0; n2 < 2; n2++) {
                int r = r0 + n2;
                float sv[4], mv[4];
                if (n2 == 0) { sv[0]=s0.x; sv[1]=s0.y; sv[2]=s0.z; sv[3]=s0.w;
                               mv[0]=m0.x; mv[1]=m0.y; mv[2]=m0.z; mv[3]=m0.w; }
                else         { sv[0]=s1.x; sv[1]=s1.y; sv[2]=s1.z; sv[3]=s1.w;
                               mv[0]=m1.x; mv[1]=m1.y; mv[2]=m1.z; mv[3]=m1.w; }
                uint32_t sh[4], sl[4], mh[4], ml[4];
                #pragma unroll
                for (int q = 0; q < 4; q++) {
                    __nv_bfloat16 h1 = __float2bfloat16_rn(sv[q]);
                    sh[q] = (uint32_t)__bfloat16_as_ushort(h1);
                    sl[q] = (uint32_t)__bfloat16_as_ushort(__float2bfloat16_rn(sv[q] - __bfloat162float(h1)));
                    __nv_bfloat16 h2 = __float2bfloat16_rn(mv[q]);
                    mh[q] = (uint32_t)__bfloat16_as_ushort(h2);
                    ml[q] = (uint32_t)__bfloat16_as_ushort(__float2bfloat16_rn(mv[q] - __bfloat162float(h2)));
                }
                uint32_t rowoff = (uint32_t)(r * 128) + (cb ^ (uint32_t)((r & 7) << 4));
                uint2 u;
                u.x = sh[0] | (sh[1] << 16); u.y = sh[2] | (sh[3] << 16);
                *(uint2*)((char*)smem + (abase_hi - sb) + csum + rowoff) = u;
                u.x = sl[0] | (sl[1] << 16); u.y = sl[2] | (sl[3] << 16);
                *(uint2*)((char*)smem + (abase_lo - sb) + csum + rowoff) = u;
                u.x = mh[0] | (mh[1] << 16); u.y = mh[2] | (mh[3] << 16);
                *(uint2*)((char*)smem + (abase_hi - sb) + cmax + rowoff) = u;
                u.x = ml[0] | (ml[1] << 16); u.y = ml[2] | (ml[3] << 16);
                *(uint2*)((char*)smem + (abase_lo - sb) + cmax + rowoff) = u;
            }
            BAR_ARRIVE(1 + buf, THREADS);
        }
    } else {
        // ===================== CONSUMER (warps 16-17, M=32 x N=64 each) =====================
        int ctid = tid - 512;           // 0..63
        int warp_n = wid - 16;          // 0..1
        // stage B (hi+lo = 128KB) with consumer threads only
        const __nv_bfloat16* Bh = g_bhi + (size_t)l * UU * K2;
        const __nv_bfloat16* Bl = g_blo + (size_t)l * UU * K2;
        #pragma unroll
        for (int t = 0; t < 128; t++) {
            int q = ctid + t * 64;      // 0..8191
            int arr = q >> 12;
            int rem = q & 4095;
            int ch = rem >> 10;
            int seg = rem & 1023;
            int row = seg >> 3, sgi = seg & 7;
            uint32_t dst = sb + (arr ? SB_LO : SB_HI) + ch * 16384 + SWZ((uint32_t)(row * 128 + sgi * 16));
            const char* src = (const char*)(arr ? Bl : Bh) + (size_t)row * 512 + ch * 128 + sgi * 16;
            cp16(dst, src);
        }
        asm volatile("cp.async.commit_group;" ::: "memory");
        float* sepi = (float*)(smem + S_EPI);
        for (int i = ctid; i < 128; i += 64) {
            sepi[i]       = __ldg(bias + i);
            sepi[128 + i] = g_bn_a[l * UU + i];
            sepi[256 + i] = g_bn_d[l * UU + i];
        }
        asm volatile("cp.async.wait_group 0;" ::: "memory");
        BAR_SYNC(5, 64);   // consumer-only: B + epi visible to both consumer warps

        uint32_t kaA = (uint32_t)((lane >> 4) * 16);
        uint32_t a_off[2], a_xor[2];
        #pragma unroll
        for (int i = 0; i < 2; i++) {
            int r = i * 16 + (lane & 15);
            a_off[i] = (uint32_t)(r * 128);
            a_xor[i] = (a_off[i] >> 3) & 0x70;
        }
        int lnB = (lane & 7) + ((lane >> 4) << 3);
        uint32_t kaB = (uint32_t)(((lane >> 3) & 1) * 16);
        uint32_t b_off[4], b_xor[4];
        #pragma unroll
        for (int p = 0; p < 4; p++) {
            int n = warp_n * 64 + p * 16 + lnB;
            b_off[p] = (uint32_t)(n * 128);
            b_xor[p] = (b_off[p] >> 3) & 0x70;
        }

        int it = 0;
        for (int tile = blockIdx.x; tile < NTILES; tile += GRIDSZ, it++) {
            int buf = it & 1;
            BAR_SYNC(1 + buf, THREADS);
            uint32_t abase_hi = sb + SA_BASE + buf * SA_BUFSZ;
            uint32_t abase_lo = abase_hi + 16384;

            float acc[2][8][4];
            #pragma unroll
            for (int i = 0; i < 2; i++)
                #pragma unroll
                for (int j = 0; j < 8; j++)
                    #pragma unroll
                    for (int q = 0; q < 4; q++) acc[i][j][q] = 0.f;

            #pragma unroll
            for (int ch = 0; ch < 4; ch++) {
                uint32_t Ah  = abase_hi + ch * 4096;
                uint32_t Al  = abase_lo + ch * 4096;
                uint32_t Bhs = sb + SB_HI + ch * 16384;
                uint32_t Bls = sb + SB_LO + ch * 16384;
                #pragma unroll
                for (int ks = 0; ks < 4; ks++) {
                    uint32_t kb = (uint32_t)(ks * 32);
                    uint32_t ahi[2][4], alo[2][4];
                    #pragma unroll
                    for (int i = 0; i < 2; i++) {
                        ldmx4(ahi[i], Ah + a_off[i] + ((kb + kaA) ^ a_xor[i]));
                        ldmx4(alo[i], Al + a_off[i] + ((kb + kaA) ^ a_xor[i]));
                    }
                    #pragma unroll
                    for (int p = 0; p < 4; p++) {
                        uint32_t bh[4], bl[4];
                        ldmx4(bh, Bhs + b_off[p] + ((kb + kaB) ^ b_xor[p]));
                        ldmx4(bl, Bls + b_off[p] + ((kb + kaB) ^ b_xor[p]));
                        #pragma unroll
                        for (int i = 0; i < 2; i++)
                            #pragma unroll
                            for (int jj = 0; jj < 2; jj++) {
                                int j = 2 * p + jj, s2 = jj * 2;
                                mma_bf16(acc[i][j], ahi[i], bh[s2], bh[s2 + 1]);
                                mma_bf16(acc[i][j], ahi[i], bl[s2], bl[s2 + 1]);
                                mma_bf16(acc[i][j], alo[i], bh[s2], bh[s2 + 1]);
                            }
                    }
                }
            }
            BAR_ARRIVE(3 + buf, THREADS);   // A buffer free; epilogue runs after

            // ---- epilogue (outside the buffer critical section) ----
            int node0 = tile * TILE_M;
            if (!fuse_readout) {
                int mbase = node0 + (lane >> 2);
                #pragma unroll
                for (int i = 0; i < 2; i++)
                    #pragma unroll
                    for (int j = 0; j < 8; j++) {
                        int col = warp_n * 64 + j * 8 + (lane & 3) * 2;
                        float b0 = sepi[col], b1 = sepi[col + 1];
                        float a0 = sepi[128 + col], a1 = sepi[128 + col + 1];
                        float d0 = sepi[256 + col], d1 = sepi[256 + col + 1];
                        int r0 = mbase + i * 16;
                        float2 o;
                        o.x = fmaxf(acc[i][j][0] + b0, 0.f) * a0 + d0;
                        o.y = fmaxf(acc[i][j][1] + b1, 0.f) * a1 + d1;
                        *(float2*)&xout[(size_t)r0 * UU + col] = o;
                        o.x = fmaxf(acc[i][j][2] + b0, 0.f) * a0 + d0;
                        o.y = fmaxf(acc[i][j][3] + b1, 0.f) * a1 + d1;
                        *(float2*)&xout[(size_t)(r0 + 8) * UU + col] = o;
                    }
            } else {
                // final layer: column-reduce post-BN values and atomicAdd to g_gm
                int b = node0 >> 12;
                float cs0[8], cs1[8];
                #pragma unroll
                for (int j = 0; j < 8; j++) { cs0[j] = 0.f; cs1[j] = 0.f; }
                #pragma unroll
                for (int i = 0; i < 2; i++)
                    #pragma unroll
                    for (int j = 0; j < 8; j++) {
                        int col = warp_n * 64 + j * 8 + (lane & 3) * 2;
                        float b0 = sepi[col], b1 = sepi[col + 1];
                        float a0 = sepi[128 + col], a1 = sepi[128 + col + 1];
                        float d0 = sepi[256 + col], d1 = sepi[256 + col + 1];
                        cs0[j] += fmaxf(acc[i][j][0] + b0, 0.f) * a0 + d0
                                + fmaxf(acc[i][j][2] + b0, 0.f) * a0 + d0;
                        cs1[j] += fmaxf(acc[i][j][1] + b1, 0.f) * a1 + d1
                                + fmaxf(acc[i][j][3] + b1, 0.f) * a1 + d1;
                    }
                #pragma unroll
                for (int j = 0; j < 8; j++) {
                    #pragma unroll
                    for (int e = 4; e < 32; e <<= 1) {
                        cs0[j] += __shfl_xor_sync(0xffffffffu, cs0[j], e);
                        cs1[j] += __shfl_xor_sync(0xffffffffu, cs1[j], e);
                    }
                }
                if (lane < 4) {
                    #pragma unroll
                    for (int j = 0; j < 8; j++) {
                        int col = warp_n * 64 + j * 8 + lane * 2;
                        atomicAdd(&g_gm[b * UU + col],     cs0[j] * (1.f / NN));
                        atomicAdd(&g_gm[b * UU + col + 1], cs1[j] * (1.f / NN));
                    }
                }
            }
        }
    }
}

// ------------------- fused projection MLP (relu(relu(g@Wp1+bp1)@Wp2+bp2)) -------------------
__global__ void mlp_kernel(const float* __restrict__ Wp1, const float* __restrict__ bp1,
                           const float* __restrict__ Wp2, const float* __restrict__ bp2,
                           float* __restrict__ out) {
    __shared__ float gs[UU];
    __shared__ float hs[UU];
    int b = blockIdx.x, j = threadIdx.x;   // 128 threads
    gs[j] = g_gm[b * UU + j];
    __syncthreads();
    float acc = bp1[j];
    #pragma unroll 8
    for (int k = 0; k < UU; k++) acc += gs[k] * Wp1[k * UU + j];
    hs[j] = fmaxf(acc, 0.f);
    __syncthreads();
    if (j < 64) {
        float a2 = bp2[j];
        #pragma unroll 8
        for (int k = 0; k < UU; k++) a2 += hs[k] * Wp2[k * 64 + j];
        out[b * 64 + j] = fmaxf(a2, 0.f);
    }
}

// ------------------- launch -------------------
extern "C" void kernel_launch(void* const* d_in, const int* in_sizes, int n_in,
                              void* d_out, int out_size) {
    const float* x0    = (const float*)d_in[0];
    const int*   ei    = (const int*)d_in[1];
    const float* W     = (const float*)d_in[2];
    const float* bvec  = (const float*)d_in[3];
    const float* gamma = (const float*)d_in[4];
    const float* beta  = (const float*)d_in[5];
    const float* mmean = (const float*)d_in[6];
    const float* mvar  = (const float*)d_in[7];
    const float* Wp1   = (const float*)d_in[8];
    const float* bp1   = (const float*)d_in[9];
    const float* Wp2   = (const float*)d_in[10];
    const float* bp2   = (const float*)d_in[11];

    cudaFuncSetAttribute(fused_layer_kernel, cudaFuncAttributeMaxDynamicSharedMemorySize, FUSED_SMEM);

    prep_kernel<<<96, 1024>>>(W, gamma, beta, mmean, mvar);

    float *xa, *xb;
    cudaGetSymbolAddress((void**)&xa, g_xa);
    cudaGetSymbolAddress((void**)&xb, g_xb);

    // l0: x0 -> xa,  l1: xa -> xb,  l2: xb -> (fused readout into g_gm)
    fused_layer_kernel<<<GRIDSZ, THREADS, FUSED_SMEM>>>(0, x0, xa, ei, bvec + 0 * UU, 0);
    fused_layer_kernel<<<GRIDSZ, THREADS, FUSED_SMEM>>>(1, xa, xb, ei, bvec + 1 * UU, 0);
    fused_layer_kernel<<<GRIDSZ, THREADS, FUSED_SMEM>>>(2, xb, xa, ei, bvec + 2 * UU, 1);

    mlp_kernel<<<BB, 128>>>(Wp1, bp1, Wp2, bp2, (float*)d_out);
}

// round 14
// speedup vs baseline: 1.6056x; 1.6056x over previous
#include <cuda_runtime.h>
#include <cuda_bf16.h>
#include <math.h>
#include <stdint.h>

#define BB 8
#define NN 4096
#define DEG 16
#define UU 128
#define EE (NN*DEG)
#define MM (BB*NN)
#define K2 256
#define DEPTH 3
#define SCALE_C 1.2304489f
#define THREADS 640
#define TILE_M 32
#define NTILES (MM/TILE_M)
#define GRIDSZ 148

// ------------------- device scratch (ping-pong bf16 feature buffers) -------------------
__device__ __nv_bfloat16 g_xa[(size_t)MM * UU];
__device__ __nv_bfloat16 g_xb[(size_t)MM * UU];
__device__ __nv_bfloat16 g_bhi[DEPTH * UU * K2];       // folded W, [n][k] K-major, hi
__device__ __nv_bfloat16 g_blo[DEPTH * UU * K2];
__device__ float g_bn_a[DEPTH * UU];
__device__ float g_bn_d[DEPTH * UU];
__device__ float g_gm[BB * UU];

// ------------------- helpers -------------------
__device__ __forceinline__ uint32_t smem_u32(const void* p) {
    uint32_t a;
    asm("{ .reg .u64 t; cvta.to.shared.u64 t, %1; cvt.u32.u64 %0, t; }" : "=r"(a) : "l"(p));
    return a;
}
__device__ __forceinline__ void cp16(uint32_t dst, const void* src) {
    asm volatile("cp.async.cg.shared.global [%0], [%1], 16;" :: "r"(dst), "l"(src) : "memory");
}
__device__ __forceinline__ void ldmx4(uint32_t* r, uint32_t addr) {
    asm volatile("ldmatrix.sync.aligned.m8n8.x4.shared.b16 {%0,%1,%2,%3}, [%4];"
                 : "=r"(r[0]), "=r"(r[1]), "=r"(r[2]), "=r"(r[3]) : "r"(addr));
}
__device__ __forceinline__ void mma_bf16(float* c, const uint32_t* a, uint32_t b0, uint32_t b1) {
    asm volatile("mma.sync.aligned.m16n8k16.row.col.f32.bf16.bf16.f32 "
                 "{%0,%1,%2,%3}, {%4,%5,%6,%7}, {%8,%9}, {%0,%1,%2,%3};"
                 : "+f"(c[0]), "+f"(c[1]), "+f"(c[2]), "+f"(c[3])
                 : "r"(a[0]), "r"(a[1]), "r"(a[2]), "r"(a[3]), "r"(b0), "r"(b1));
}
__device__ __forceinline__ float4 bf4_to_f4(uint2 u) {
    __nv_bfloat162 p0 = *reinterpret_cast<__nv_bfloat162*>(&u.x);
    __nv_bfloat162 p1 = *reinterpret_cast<__nv_bfloat162*>(&u.y);
    float2 f0 = __bfloat1622float2(p0);
    float2 f1 = __bfloat1622float2(p1);
    return make_float4(f0.x, f0.y, f1.x, f1.y);
}
#define SWZ(off) ((off) ^ (((off) >> 3) & 0x70))
#define BAR_SYNC(id, cnt)   asm volatile("bar.sync %0, %1;"   :: "r"(id), "r"(cnt) : "memory")
#define BAR_ARRIVE(id, cnt) asm volatile("bar.arrive %0, %1;" :: "r"(id), "r"(cnt) : "memory")

// ------------------- prep: weight folding + BN fold + g_gm zero (one kernel) -------------------
__global__ void prep_kernel(const float* __restrict__ W,
                            const float* __restrict__ gamma, const float* __restrict__ beta,
                            const float* __restrict__ mm, const float* __restrict__ mv) {
    int t = blockIdx.x * blockDim.x + threadIdx.x;
    if (t < BB * UU) g_gm[t] = 0.f;
    if (t < DEPTH * UU) {
        float a = gamma[t] * rsqrtf(mv[t] + 1e-3f);
        g_bn_a[t] = a;
        g_bn_d[t] = beta[t] - mm[t] * a;
    }
    if (t >= DEPTH * K2 * UU) return;
    int j = t & 127;          // output feature n
    int k = (t >> 7) & 255;   // k index
    int l = t >> 15;
    const float c = SCALE_C;
    const float* Wl = W + (size_t)l * 1152 * UU;
    float v;
    if (k < 128) {
        float w0 = Wl[(0 * 128 + k) * UU + j];
        float w1 = Wl[(1 * 128 + k) * UU + j];
        float w2 = Wl[(2 * 128 + k) * UU + j];
        float w6 = Wl[(6 * 128 + k) * UU + j];
        float w7 = Wl[(7 * 128 + k) * UU + j];
        float w8 = Wl[(8 * 128 + k) * UU + j];
        v = (w0 + c * (w1 + w2)) * 0.0625f + w6 + c * (w7 + w8);
    } else {
        int kk = k - 128;
        float w3 = Wl[(3 * 128 + kk) * UU + j];
        float w4 = Wl[(4 * 128 + kk) * UU + j];
        float w5 = Wl[(5 * 128 + kk) * UU + j];
        v = w3 + c * (w4 + w5);
    }
    __nv_bfloat16 hi = __float2bfloat16_rn(v);
    size_t o = (size_t)l * UU * K2 + (size_t)j * K2 + k;
    g_bhi[o] = hi;
    g_blo[o] = __float2bfloat16_rn(v - __bfloat162float(hi));
}

// ------------------- warp-specialized fused layer kernel -------------------
// 640 threads: warps 0-15 produce (gather->A smem, 2 nodes each, depth-2 prefetch),
// warps 16-19 consume (MMA M=32 x N=32 slice each + epilogue).
// Tile M=32, N=128, K=256. A double-buffered (2x32KB), B resident (128KB).
// xin32 != nullptr -> fp32 gather (layer 0); else bf16 gather from xin16.
// fuse_readout: column-reduce into g_gm instead of writing xout.
#define SB_HI   0
#define SB_LO   65536
#define SA_BASE 131072
#define SA_BUFSZ 32768
#define S_EPI   (131072 + 2*SA_BUFSZ)
#define FUSED_SMEM (S_EPI + 3*128*4)
// named barriers: full[buf]=1+buf, empty[buf]=3+buf, consumer-init=5

__global__ __launch_bounds__(THREADS, 1) void fused_layer_kernel(
        int l, const float* __restrict__ xin32, const __nv_bfloat16* __restrict__ xin16,
        __nv_bfloat16* __restrict__ xout,
        const int* __restrict__ ei, const float* __restrict__ bias,
        int fuse_readout) {
    extern __shared__ __align__(1024) char smem[];
    uint32_t sb = smem_u32(smem);
    int tid = threadIdx.x, lane = tid & 31, wid = tid >> 5;

    if (wid < 16) {
        // ===================== PRODUCER (16 warps, 2 nodes each) =====================
        const float ninf = __int_as_float(0xff800000);
        uint32_t csum = (uint32_t)(lane >> 4) * 4096;       // ssum chunk (0 or 1)
        uint32_t cmax = csum + 2 * 4096;                    // smax chunk (2 or 3)
        uint32_t cb   = (uint32_t)(lane & 15) * 8;
        int r0 = wid * 2;                                    // 2 nodes per warp

        int it = 0;
        for (int tile = blockIdx.x; tile < NTILES; tile += GRIDSZ, it++) {
            int buf = it & 1;
            if (it >= 2) BAR_SYNC(3 + buf, THREADS);
            uint32_t abase_hi = sb + SA_BASE + buf * SA_BUFSZ;
            uint32_t abase_lo = abase_hi + 16384;

            int node0 = tile * TILE_M;
            int b = node0 >> 12;
            int nd0 = node0 & (NN - 1);
            const int* ep = ei + 2 * ((size_t)b * EE + (size_t)(nd0 + r0) * DEG);

            int myd0 = (lane < DEG) ? ep[2 * lane + 1] : 0;
            int myd1 = (lane < DEG) ? ep[2 * DEG + 2 * lane + 1] : 0;

            float4 s0 = make_float4(0.f, 0.f, 0.f, 0.f);
            float4 s1 = make_float4(0.f, 0.f, 0.f, 0.f);
            float4 m0 = make_float4(ninf, ninf, ninf, ninf);
            float4 m1 = make_float4(ninf, ninf, ninf, ninf);

            if (xin32) {
                // fp32 gather, depth-2 prefetch
                const float* xb = xin32 + (size_t)b * NN * UU;
                float4 pf[2][2];
                #pragma unroll
                for (int pe = 0; pe < 2; pe++) {
                    int d0 = __shfl_sync(0xffffffffu, myd0, pe);
                    int d1 = __shfl_sync(0xffffffffu, myd1, pe);
                    pf[pe][0] = __ldg((const float4*)(xb + (size_t)d0 * UU + lane * 4));
                    pf[pe][1] = __ldg((const float4*)(xb + (size_t)d1 * UU + lane * 4));
                }
                #pragma unroll
                for (int e = 0; e < DEG; e++) {
                    int nb = e & 1;
                    float4 v0 = pf[nb][0];
                    float4 v1 = pf[nb][1];
                    if (e + 2 < DEG) {
                        int d0 = __shfl_sync(0xffffffffu, myd0, e + 2);
                        int d1 = __shfl_sync(0xffffffffu, myd1, e + 2);
                        pf[nb][0] = __ldg((const float4*)(xb + (size_t)d0 * UU + lane * 4));
                        pf[nb][1] = __ldg((const float4*)(xb + (size_t)d1 * UU + lane * 4));
                    }
                    s0.x += v0.x; s0.y += v0.y; s0.z += v0.z; s0.w += v0.w;
                    m0.x = fmaxf(m0.x, v0.x); m0.y = fmaxf(m0.y, v0.y);
                    m0.z = fmaxf(m0.z, v0.z); m0.w = fmaxf(m0.w, v0.w);
                    s1.x += v1.x; s1.y += v1.y; s1.z += v1.z; s1.w += v1.w;
                    m1.x = fmaxf(m1.x, v1.x); m1.y = fmaxf(m1.y, v1.y);
                    m1.z = fmaxf(m1.z, v1.z); m1.w = fmaxf(m1.w, v1.w);
                }
            } else {
                // bf16 gather (half the bytes), depth-2 prefetch
                const __nv_bfloat16* xh = xin16 + (size_t)b * NN * UU;
                uint2 pf[2][2];
                #pragma unroll
                for (int pe = 0; pe < 2; pe++) {
                    int d0 = __shfl_sync(0xffffffffu, myd0, pe);
                    int d1 = __shfl_sync(0xffffffffu, myd1, pe);
                    pf[pe][0] = __ldg((const uint2*)(xh + (size_t)d0 * UU + lane * 4));
                    pf[pe][1] = __ldg((const uint2*)(xh + (size_t)d1 * UU + lane * 4));
                }
                #pragma unroll
                for (int e = 0; e < DEG; e++) {
                    int nb = e & 1;
                    float4 v0 = bf4_to_f4(pf[nb][0]);
                    float4 v1 = bf4_to_f4(pf[nb][1]);
                    if (e + 2 < DEG) {
                        int d0 = __shfl_sync(0xffffffffu, myd0, e + 2);
                        int d1 = __shfl_sync(0xffffffffu, myd1, e + 2);
                        pf[nb][0] = __ldg((const uint2*)(xh + (size_t)d0 * UU + lane * 4));
                        pf[nb][1] = __ldg((const uint2*)(xh + (size_t)d1 * UU + lane * 4));
                    }
                    s0.x += v0.x; s0.y += v0.y; s0.z += v0.z; s0.w += v0.w;
                    m0.x = fmaxf(m0.x, v0.x); m0.y = fmaxf(m0.y, v0.y);
                    m0.z = fmaxf(m0.z, v0.z); m0.w = fmaxf(m0.w, v0.w);
                    s1.x += v1.x; s1.y += v1.y; s1.z += v1.z; s1.w += v1.w;
                    m1.x = fmaxf(m1.x, v1.x); m1.y = fmaxf(m1.y, v1.y);
                    m1.z = fmaxf(m1.z, v1.z); m1.w = fmaxf(m1.w, v1.w);
                }
            }

            #pragma unroll
            for (int n2 = 0; n2 < 2; n2++) {
                int r = r0 + n2;
                float sv[4], mv[4];
                if (n2 == 0) { sv[0]=s0.x; sv[1]=s0.y; sv[2]=s0.z; sv[3]=s0.w;
                               mv[0]=m0.x; mv[1]=m0.y; mv[2]=m0.z; mv[3]=m0.w; }
                else         { sv[0]=s1.x; sv[1]=s1.y; sv[2]=s1.z; sv[3]=s1.w;
                               mv[0]=m1.x; mv[1]=m1.y; mv[2]=m1.z; mv[3]=m1.w; }
                uint32_t sh[4], sl[4], mh[4], ml[4];
                #pragma unroll
                for (int q = 0; q < 4; q++) {
                    __nv_bfloat16 h1 = __float2bfloat16_rn(sv[q]);
                    sh[q] = (uint32_t)__bfloat16_as_ushort(h1);
                    sl[q] = (uint32_t)__bfloat16_as_ushort(__float2bfloat16_rn(sv[q] - __bfloat162float(h1)));
                    __nv_bfloat16 h2 = __float2bfloat16_rn(mv[q]);
                    mh[q] = (uint32_t)__bfloat16_as_ushort(h2);
                    ml[q] = (uint32_t)__bfloat16_as_ushort(__float2bfloat16_rn(mv[q] - __bfloat162float(h2)));
                }
                uint32_t rowoff = (uint32_t)(r * 128) + (cb ^ (uint32_t)((r & 7) << 4));
                uint2 u;
                u.x = sh[0] | (sh[1] << 16); u.y = sh[2] | (sh[3] << 16);
                *(uint2*)((char*)smem + (abase_hi - sb) + csum + rowoff) = u;
                u.x = sl[0] | (sl[1] << 16); u.y = sl[2] | (sl[3] << 16);
                *(uint2*)((char*)smem + (abase_lo - sb) + csum + rowoff) = u;
                u.x = mh[0] | (mh[1] << 16); u.y = mh[2] | (mh[3] << 16);
                *(uint2*)((char*)smem + (abase_hi - sb) + cmax + rowoff) = u;
                u.x = ml[0] | (ml[1] << 16); u.y = ml[2] | (ml[3] << 16);
                *(uint2*)((char*)smem + (abase_lo - sb) + cmax + rowoff) = u;
            }
            BAR_ARRIVE(1 + buf, THREADS);
        }
    } else {
        // ===================== CONSUMER (warps 16-19) =====================
        int ctid = tid - 512;           // 0..127
        int warp_n = wid - 16;          // 0..3, N=32 slice each; M=32 full
        // stage B (hi+lo = 128KB) with consumer threads only
        const __nv_bfloat16* Bh = g_bhi + (size_t)l * UU * K2;
        const __nv_bfloat16* Bl = g_blo + (size_t)l * UU * K2;
        #pragma unroll
        for (int t = 0; t < 64; t++) {
            int q = ctid + t * 128;     // 0..8191
            int arr = q >> 12;
            int rem = q & 4095;
            int ch = rem >> 10;
            int seg = rem & 1023;
            int row = seg >> 3, sgi = seg & 7;
            uint32_t dst = sb + (arr ? SB_LO : SB_HI) + ch * 16384 + SWZ((uint32_t)(row * 128 + sgi * 16));
            const char* src = (const char*)(arr ? Bl : Bh) + (size_t)row * 512 + ch * 128 + sgi * 16;
            cp16(dst, src);
        }
        asm volatile("cp.async.commit_group;" ::: "memory");
        float* sepi = (float*)(smem + S_EPI);
        if (ctid < 128) {
            sepi[ctid]       = __ldg(bias + ctid);
            sepi[128 + ctid] = g_bn_a[l * UU + ctid];
            sepi[256 + ctid] = g_bn_d[l * UU + ctid];
        }
        asm volatile("cp.async.wait_group 0;" ::: "memory");
        BAR_SYNC(5, 128);   // consumer-only: B + epi visible to all consumer warps

        uint32_t kaA = (uint32_t)((lane >> 4) * 16);
        uint32_t a_off[2], a_xor[2];
        #pragma unroll
        for (int i = 0; i < 2; i++) {
            int r = i * 16 + (lane & 15);
            a_off[i] = (uint32_t)(r * 128);
            a_xor[i] = (a_off[i] >> 3) & 0x70;
        }
        int lnB = (lane & 7) + ((lane >> 4) << 3);
        uint32_t kaB = (uint32_t)(((lane >> 3) & 1) * 16);
        uint32_t b_off[2], b_xor[2];
        #pragma unroll
        for (int p = 0; p < 2; p++) {
            int n = warp_n * 32 + p * 16 + lnB;
            b_off[p] = (uint32_t)(n * 128);
            b_xor[p] = (b_off[p] >> 3) & 0x70;
        }

        int it = 0;
        for (int tile = blockIdx.x; tile < NTILES; tile += GRIDSZ, it++) {
            int buf = it & 1;
            BAR_SYNC(1 + buf, THREADS);
            uint32_t abase_hi = sb + SA_BASE + buf * SA_BUFSZ;
            uint32_t abase_lo = abase_hi + 16384;

            float acc[2][4][4];
            #pragma unroll
            for (int i = 0; i < 2; i++)
                #pragma unroll
                for (int j = 0; j < 4; j++)
                    #pragma unroll
                    for (int q = 0; q < 4; q++) acc[i][j][q] = 0.f;

            #pragma unroll
            for (int ch = 0; ch < 4; ch++) {
                uint32_t Ah  = abase_hi + ch * 4096;
                uint32_t Al  = abase_lo + ch * 4096;
                uint32_t Bhs = sb + SB_HI + ch * 16384;
                uint32_t Bls = sb + SB_LO + ch * 16384;
                #pragma unroll
                for (int ks = 0; ks < 4; ks++) {
                    uint32_t kb = (uint32_t)(ks * 32);
                    uint32_t ahi[2][4], alo[2][4], bhi[2][4], blo[2][4];
                    #pragma unroll
                    for (int i = 0; i < 2; i++) {
                        ldmx4(ahi[i], Ah + a_off[i] + ((kb + kaA) ^ a_xor[i]));
                        ldmx4(alo[i], Al + a_off[i] + ((kb + kaA) ^ a_xor[i]));
                    }
                    #pragma unroll
                    for (int p = 0; p < 2; p++) {
                        ldmx4(bhi[p], Bhs + b_off[p] + ((kb + kaB) ^ b_xor[p]));
                        ldmx4(blo[p], Bls + b_off[p] + ((kb + kaB) ^ b_xor[p]));
                    }
                    #pragma unroll
                    for (int i = 0; i < 2; i++)
                        #pragma unroll
                        for (int j = 0; j < 4; j++) {
                            int p = j >> 1, s2 = (j & 1) * 2;
                            mma_bf16(acc[i][j], ahi[i], bhi[p][s2], bhi[p][s2 + 1]);
                            mma_bf16(acc[i][j], ahi[i], blo[p][s2], blo[p][s2 + 1]);
                            mma_bf16(acc[i][j], alo[i], bhi[p][s2], bhi[p][s2 + 1]);
                        }
                }
            }
            BAR_ARRIVE(3 + buf, THREADS);   // A buffer free; epilogue runs after

            // ---- epilogue (outside the buffer critical section) ----
            int node0 = tile * TILE_M;
            if (!fuse_readout) {
                int mbase = node0 + (lane >> 2);
                #pragma unroll
                for (int i = 0; i < 2; i++)
                    #pragma unroll
                    for (int j = 0; j < 4; j++) {
                        int col = warp_n * 32 + j * 8 + (lane & 3) * 2;
                        float b0 = sepi[col], b1 = sepi[col + 1];
                        float a0 = sepi[128 + col], a1 = sepi[128 + col + 1];
                        float d0 = sepi[256 + col], d1 = sepi[256 + col + 1];
                        int r0 = mbase + i * 16;
                        float o0 = fmaxf(acc[i][j][0] + b0, 0.f) * a0 + d0;
                        float o1 = fmaxf(acc[i][j][1] + b1, 0.f) * a1 + d1;
                        *(__nv_bfloat162*)&xout[(size_t)r0 * UU + col] = __floats2bfloat162_rn(o0, o1);
                        o0 = fmaxf(acc[i][j][2] + b0, 0.f) * a0 + d0;
                        o1 = fmaxf(acc[i][j][3] + b1, 0.f) * a1 + d1;
                        *(__nv_bfloat162*)&xout[(size_t)(r0 + 8) * UU + col] = __floats2bfloat162_rn(o0, o1);
                    }
            } else {
                // final layer: column-reduce post-BN values (fp32) and atomicAdd to g_gm
                int b = node0 >> 12;
                float cs0[4], cs1[4];
                #pragma unroll
                for (int j = 0; j < 4; j++) { cs0[j] = 0.f; cs1[j] = 0.f; }
                #pragma unroll
                for (int i = 0; i < 2; i++)
                    #pragma unroll
                    for (int j = 0; j < 4; j++) {
                        int col = warp_n * 32 + j * 8 + (lane & 3) * 2;
                        float b0 = sepi[col], b1 = sepi[col + 1];
                        float a0 = sepi[128 + col], a1 = sepi[128 + col + 1];
                        float d0 = sepi[256 + col], d1 = sepi[256 + col + 1];
                        cs0[j] += fmaxf(acc[i][j][0] + b0, 0.f) * a0 + d0
                                + fmaxf(acc[i][j][2] + b0, 0.f) * a0 + d0;
                        cs1[j] += fmaxf(acc[i][j][1] + b1, 0.f) * a1 + d1
                                + fmaxf(acc[i][j][3] + b1, 0.f) * a1 + d1;
                    }
                #pragma unroll
                for (int j = 0; j < 4; j++) {
                    #pragma unroll
                    for (int e = 4; e < 32; e <<= 1) {
                        cs0[j] += __shfl_xor_sync(0xffffffffu, cs0[j], e);
                        cs1[j] += __shfl_xor_sync(0xffffffffu, cs1[j], e);
                    }
                }
                if (lane < 4) {
                    #pragma unroll
                    for (int j = 0; j < 4; j++) {
                        int col = warp_n * 32 + j * 8 + lane * 2;
                        atomicAdd(&g_gm[b * UU + col],     cs0[j] * (1.f / NN));
                        atomicAdd(&g_gm[b * UU + col + 1], cs1[j] * (1.f / NN));
                    }
                }
            }
        }
    }
}

// ------------------- fused projection MLP (relu(relu(g@Wp1+bp1)@Wp2+bp2)) -------------------
__global__ void mlp_kernel(const float* __restrict__ Wp1, const float* __restrict__ bp1,
                           const float* __restrict__ Wp2, const float* __restrict__ bp2,
                           float* __restrict__ out) {
    __shared__ float gs[UU];
    __shared__ float hs[UU];
    int b = blockIdx.x, j = threadIdx.x;   // 128 threads
    gs[j] = g_gm[b * UU + j];
    __syncthreads();
    float acc = bp1[j];
    #pragma unroll 8
    for (int k = 0; k < UU; k++) acc += gs[k] * Wp1[k * UU + j];
    hs[j] = fmaxf(acc, 0.f);
    __syncthreads();
    if (j < 64) {
        float a2 = bp2[j];
        #pragma unroll 8
        for (int k = 0; k < UU; k++) a2 += hs[k] * Wp2[k * 64 + j];
        out[b * 64 + j] = fmaxf(a2, 0.f);
    }
}

// ------------------- launch -------------------
extern "C" void kernel_launch(void* const* d_in, const int* in_sizes, int n_in,
                              void* d_out, int out_size) {
    const float* x0    = (const float*)d_in[0];
    const int*   ei    = (const int*)d_in[1];
    const float* W     = (const float*)d_in[2];
    const float* bvec  = (const float*)d_in[3];
    const float* gamma = (const float*)d_in[4];
    const float* beta  = (const float*)d_in[5];
    const float* mmean = (const float*)d_in[6];
    const float* mvar  = (const float*)d_in[7];
    const float* Wp1   = (const float*)d_in[8];
    const float* bp1   = (const float*)d_in[9];
    const float* Wp2   = (const float*)d_in[10];
    const float* bp2   = (const float*)d_in[11];

    cudaFuncSetAttribute(fused_layer_kernel, cudaFuncAttributeMaxDynamicSharedMemorySize, FUSED_SMEM);

    prep_kernel<<<96, 1024>>>(W, gamma, beta, mmean, mvar);

    __nv_bfloat16 *xa, *xb;
    cudaGetSymbolAddress((void**)&xa, g_xa);
    cudaGetSymbolAddress((void**)&xb, g_xb);

    // l0: fp32 x0 -> bf16 xa,  l1: xa -> xb,  l2: xb -> (fused readout into g_gm)
    fused_layer_kernel<<<GRIDSZ, THREADS, FUSED_SMEM>>>(
        0, x0, (const __nv_bfloat16*)nullptr, xa, ei, bvec + 0 * UU, 0);
    fused_layer_kernel<<<GRIDSZ, THREADS, FUSED_SMEM>>>(
        1, (const float*)nullptr, xa, xb, ei, bvec + 1 * UU, 0);
    fused_layer_kernel<<<GRIDSZ, THREADS, FUSED_SMEM>>>(
        2, (const float*)nullptr, xb, xa, ei, bvec + 2 * UU, 1);

    mlp_kernel<<<BB, 128>>>(Wp1, bp1, Wp2, bp2, (float*)d_out);
}

// round 15
// speedup vs baseline: 1.6494x; 1.0273x over previous
#include <cuda_runtime.h>
#include <cuda_bf16.h>
#include <math.h>
#include <stdint.h>

#define BB 8
#define NN 4096
#define DEG 16
#define UU 128
#define EE (NN*DEG)
#define MM (BB*NN)
#define K2 256
#define DEPTH 3
#define SCALE_C 1.2304489f
#define THREADS 640
#define TILE_M 32
#define NTILES (MM/TILE_M)
#define GRIDSZ 148

// ------------------- device scratch (ping-pong bf16 feature buffers) -------------------
__device__ __nv_bfloat16 g_xa[(size_t)MM * UU];
__device__ __nv_bfloat16 g_xb[(size_t)MM * UU];
__device__ __nv_bfloat16 g_bhi[DEPTH * UU * K2];       // folded W, [n][k] K-major, hi
__device__ __nv_bfloat16 g_blo[DEPTH * UU * K2];
__device__ float g_bn_a[DEPTH * UU];
__device__ float g_bn_d[DEPTH * UU];
__device__ float g_gm[BB * UU];

// ------------------- helpers -------------------
__device__ __forceinline__ uint32_t smem_u32(const void* p) {
    uint32_t a;
    asm("{ .reg .u64 t; cvta.to.shared.u64 t, %1; cvt.u32.u64 %0, t; }" : "=r"(a) : "l"(p));
    return a;
}
__device__ __forceinline__ void cp16(uint32_t dst, const void* src) {
    asm volatile("cp.async.cg.shared.global [%0], [%1], 16;" :: "r"(dst), "l"(src) : "memory");
}
__device__ __forceinline__ void ldmx4(uint32_t* r, uint32_t addr) {
    asm volatile("ldmatrix.sync.aligned.m8n8.x4.shared.b16 {%0,%1,%2,%3}, [%4];"
                 : "=r"(r[0]), "=r"(r[1]), "=r"(r[2]), "=r"(r[3]) : "r"(addr));
}
__device__ __forceinline__ void mma_bf16(float* c, const uint32_t* a, uint32_t b0, uint32_t b1) {
    asm volatile("mma.sync.aligned.m16n8k16.row.col.f32.bf16.bf16.f32 "
                 "{%0,%1,%2,%3}, {%4,%5,%6,%7}, {%8,%9}, {%0,%1,%2,%3};"
                 : "+f"(c[0]), "+f"(c[1]), "+f"(c[2]), "+f"(c[3])
                 : "r"(a[0]), "r"(a[1]), "r"(a[2]), "r"(a[3]), "r"(b0), "r"(b1));
}
__device__ __forceinline__ float4 bf4_to_f4(uint2 u) {
    __nv_bfloat162 p0 = *reinterpret_cast<__nv_bfloat162*>(&u.x);
    __nv_bfloat162 p1 = *reinterpret_cast<__nv_bfloat162*>(&u.y);
    float2 f0 = __bfloat1622float2(p0);
    float2 f1 = __bfloat1622float2(p1);
    return make_float4(f0.x, f0.y, f1.x, f1.y);
}
#define SWZ(off) ((off) ^ (((off) >> 3) & 0x70))
#define BAR_SYNC(id, cnt)   asm volatile("bar.sync %0, %1;"   :: "r"(id), "r"(cnt) : "memory")
#define BAR_ARRIVE(id, cnt) asm volatile("bar.arrive %0, %1;" :: "r"(id), "r"(cnt) : "memory")

// ------------------- prep: weight folding + BN fold + g_gm zero (one kernel) -------------------
__global__ void prep_kernel(const float* __restrict__ W,
                            const float* __restrict__ gamma, const float* __restrict__ beta,
                            const float* __restrict__ mm, const float* __restrict__ mv) {
    int t = blockIdx.x * blockDim.x + threadIdx.x;
    if (t < BB * UU) g_gm[t] = 0.f;
    if (t < DEPTH * UU) {
        float a = gamma[t] * rsqrtf(mv[t] + 1e-3f);
        g_bn_a[t] = a;
        g_bn_d[t] = beta[t] - mm[t] * a;
    }
    if (t >= DEPTH * K2 * UU) return;
    int j = t & 127;          // output feature n
    int k = (t >> 7) & 255;   // k index
    int l = t >> 15;
    const float c = SCALE_C;
    const float* Wl = W + (size_t)l * 1152 * UU;
    float v;
    if (k < 128) {
        float w0 = Wl[(0 * 128 + k) * UU + j];
        float w1 = Wl[(1 * 128 + k) * UU + j];
        float w2 = Wl[(2 * 128 + k) * UU + j];
        float w6 = Wl[(6 * 128 + k) * UU + j];
        float w7 = Wl[(7 * 128 + k) * UU + j];
        float w8 = Wl[(8 * 128 + k) * UU + j];
        v = (w0 + c * (w1 + w2)) * 0.0625f + w6 + c * (w7 + w8);
    } else {
        int kk = k - 128;
        float w3 = Wl[(3 * 128 + kk) * UU + j];
        float w4 = Wl[(4 * 128 + kk) * UU + j];
        float w5 = Wl[(5 * 128 + kk) * UU + j];
        v = w3 + c * (w4 + w5);
    }
    __nv_bfloat16 hi = __float2bfloat16_rn(v);
    size_t o = (size_t)l * UU * K2 + (size_t)j * K2 + k;
    g_bhi[o] = hi;
    g_blo[o] = __float2bfloat16_rn(v - __bfloat162float(hi));
}

// ------------------- warp-specialized fused layer kernel -------------------
// 640 threads: warps 0-15 produce (gather->A smem), warps 16-19 consume (MMA + epilogue).
// Tile M=32, N=128, K=256. A double-buffered (2x32KB), B resident (128KB).
// xin32 != nullptr -> fp32 gather (layer 0). bf16 layers: max aggregated in native
// bf16 (hmax2, exact) -> max-lo residual is identically zero: producer skips that
// split+store, consumer skips alo LDSM + alo*bhi MMA for k-chunks 2-3.
#define SB_HI   0
#define SB_LO   65536
#define SA_BASE 131072
#define SA_BUFSZ 32768
#define S_EPI   (131072 + 2*SA_BUFSZ)
#define FUSED_SMEM (S_EPI + 3*128*4)
// named barriers: full[buf]=1+buf, empty[buf]=3+buf, consumer-init=5

__global__ __launch_bounds__(THREADS, 1) void fused_layer_kernel(
        int l, const float* __restrict__ xin32, const __nv_bfloat16* __restrict__ xin16,
        __nv_bfloat16* __restrict__ xout,
        const int* __restrict__ ei, const float* __restrict__ bias,
        int fuse_readout) {
    extern __shared__ __align__(1024) char smem[];
    uint32_t sb = smem_u32(smem);
    int tid = threadIdx.x, lane = tid & 31, wid = tid >> 5;

    if (wid < 16) {
        // ===================== PRODUCER (16 warps, 2 nodes each) =====================
        const float ninf = __int_as_float(0xff800000);
        uint32_t csum = (uint32_t)(lane >> 4) * 4096;       // ssum chunk (0 or 1)
        uint32_t cmax = csum + 2 * 4096;                    // smax chunk (2 or 3)
        uint32_t cb   = (uint32_t)(lane & 15) * 8;
        int r0 = wid * 2;                                    // 2 nodes per warp

        int it = 0;
        for (int tile = blockIdx.x; tile < NTILES; tile += GRIDSZ, it++) {
            int buf = it & 1;
            if (it >= 2) BAR_SYNC(3 + buf, THREADS);
            uint32_t abase_hi = sb + SA_BASE + buf * SA_BUFSZ;
            uint32_t abase_lo = abase_hi + 16384;

            int node0 = tile * TILE_M;
            int b = node0 >> 12;
            int nd0 = node0 & (NN - 1);
            const int* ep = ei + 2 * ((size_t)b * EE + (size_t)(nd0 + r0) * DEG);

            int myd0 = (lane < DEG) ? ep[2 * lane + 1] : 0;
            int myd1 = (lane < DEG) ? ep[2 * DEG + 2 * lane + 1] : 0;

            if (xin32) {
                // -------- fp32 gather (layer 0), depth-2 prefetch, full split --------
                const float* xb = xin32 + (size_t)b * NN * UU;
                float4 s0 = make_float4(0.f, 0.f, 0.f, 0.f);
                float4 s1 = make_float4(0.f, 0.f, 0.f, 0.f);
                float4 m0 = make_float4(ninf, ninf, ninf, ninf);
                float4 m1 = make_float4(ninf, ninf, ninf, ninf);
                float4 pf[2][2];
                #pragma unroll
                for (int pe = 0; pe < 2; pe++) {
                    int d0 = __shfl_sync(0xffffffffu, myd0, pe);
                    int d1 = __shfl_sync(0xffffffffu, myd1, pe);
                    pf[pe][0] = __ldg((const float4*)(xb + (size_t)d0 * UU + lane * 4));
                    pf[pe][1] = __ldg((const float4*)(xb + (size_t)d1 * UU + lane * 4));
                }
                #pragma unroll
                for (int e = 0; e < DEG; e++) {
                    int nb = e & 1;
                    float4 v0 = pf[nb][0];
                    float4 v1 = pf[nb][1];
                    if (e + 2 < DEG) {
                        int d0 = __shfl_sync(0xffffffffu, myd0, e + 2);
                        int d1 = __shfl_sync(0xffffffffu, myd1, e + 2);
                        pf[nb][0] = __ldg((const float4*)(xb + (size_t)d0 * UU + lane * 4));
                        pf[nb][1] = __ldg((const float4*)(xb + (size_t)d1 * UU + lane * 4));
                    }
                    s0.x += v0.x; s0.y += v0.y; s0.z += v0.z; s0.w += v0.w;
                    m0.x = fmaxf(m0.x, v0.x); m0.y = fmaxf(m0.y, v0.y);
                    m0.z = fmaxf(m0.z, v0.z); m0.w = fmaxf(m0.w, v0.w);
                    s1.x += v1.x; s1.y += v1.y; s1.z += v1.z; s1.w += v1.w;
                    m1.x = fmaxf(m1.x, v1.x); m1.y = fmaxf(m1.y, v1.y);
                    m1.z = fmaxf(m1.z, v1.z); m1.w = fmaxf(m1.w, v1.w);
                }
                #pragma unroll
                for (int n2 = 0; n2 < 2; n2++) {
                    int r = r0 + n2;
                    float sv[4], mv[4];
                    if (n2 == 0) { sv[0]=s0.x; sv[1]=s0.y; sv[2]=s0.z; sv[3]=s0.w;
                                   mv[0]=m0.x; mv[1]=m0.y; mv[2]=m0.z; mv[3]=m0.w; }
                    else         { sv[0]=s1.x; sv[1]=s1.y; sv[2]=s1.z; sv[3]=s1.w;
                                   mv[0]=m1.x; mv[1]=m1.y; mv[2]=m1.z; mv[3]=m1.w; }
                    uint32_t sh[4], sl[4], mh[4], ml[4];
                    #pragma unroll
                    for (int q = 0; q < 4; q++) {
                        __nv_bfloat16 h1 = __float2bfloat16_rn(sv[q]);
                        sh[q] = (uint32_t)__bfloat16_as_ushort(h1);
                        sl[q] = (uint32_t)__bfloat16_as_ushort(__float2bfloat16_rn(sv[q] - __bfloat162float(h1)));
                        __nv_bfloat16 h2 = __float2bfloat16_rn(mv[q]);
                        mh[q] = (uint32_t)__bfloat16_as_ushort(h2);
                        ml[q] = (uint32_t)__bfloat16_as_ushort(__float2bfloat16_rn(mv[q] - __bfloat162float(h2)));
                    }
                    uint32_t rowoff = (uint32_t)(r * 128) + (cb ^ (uint32_t)((r & 7) << 4));
                    uint2 u;
                    u.x = sh[0] | (sh[1] << 16); u.y = sh[2] | (sh[3] << 16);
                    *(uint2*)((char*)smem + (abase_hi - sb) + csum + rowoff) = u;
                    u.x = sl[0] | (sl[1] << 16); u.y = sl[2] | (sl[3] << 16);
                    *(uint2*)((char*)smem + (abase_lo - sb) + csum + rowoff) = u;
                    u.x = mh[0] | (mh[1] << 16); u.y = mh[2] | (mh[3] << 16);
                    *(uint2*)((char*)smem + (abase_hi - sb) + cmax + rowoff) = u;
                    u.x = ml[0] | (ml[1] << 16); u.y = ml[2] | (ml[3] << 16);
                    *(uint2*)((char*)smem + (abase_lo - sb) + cmax + rowoff) = u;
                }
            } else {
                // -------- bf16 gather, depth-4 prefetch, hmax2 max (exact, lo==0) --------
                const __nv_bfloat16* xh = xin16 + (size_t)b * NN * UU;
                float4 s0 = make_float4(0.f, 0.f, 0.f, 0.f);
                float4 s1 = make_float4(0.f, 0.f, 0.f, 0.f);
                __nv_bfloat162 m0a, m0b, m1a, m1b;
                {
                    uint32_t ni = 0xFF80FF80u;   // packed bf16 -inf
                    m0a = *reinterpret_cast<__nv_bfloat162*>(&ni);
                    m0b = m0a; m1a = m0a; m1b = m0a;
                }
                uint2 pf[4][2];
                #pragma unroll
                for (int pe = 0; pe < 4; pe++) {
                    int d0 = __shfl_sync(0xffffffffu, myd0, pe);
                    int d1 = __shfl_sync(0xffffffffu, myd1, pe);
                    pf[pe][0] = __ldg((const uint2*)(xh + (size_t)d0 * UU + lane * 4));
                    pf[pe][1] = __ldg((const uint2*)(xh + (size_t)d1 * UU + lane * 4));
                }
                #pragma unroll
                for (int e = 0; e < DEG; e++) {
                    int slot = e & 3;
                    uint2 v0 = pf[slot][0];
                    uint2 v1 = pf[slot][1];
                    if (e + 4 < DEG) {
                        int d0 = __shfl_sync(0xffffffffu, myd0, e + 4);
                        int d1 = __shfl_sync(0xffffffffu, myd1, e + 4);
                        pf[slot][0] = __ldg((const uint2*)(xh + (size_t)d0 * UU + lane * 4));
                        pf[slot][1] = __ldg((const uint2*)(xh + (size_t)d1 * UU + lane * 4));
                    }
                    m0a = __hmax2(m0a, *reinterpret_cast<__nv_bfloat162*>(&v0.x));
                    m0b = __hmax2(m0b, *reinterpret_cast<__nv_bfloat162*>(&v0.y));
                    m1a = __hmax2(m1a, *reinterpret_cast<__nv_bfloat162*>(&v1.x));
                    m1b = __hmax2(m1b, *reinterpret_cast<__nv_bfloat162*>(&v1.y));
                    float4 f0 = bf4_to_f4(v0);
                    float4 f1 = bf4_to_f4(v1);
                    s0.x += f0.x; s0.y += f0.y; s0.z += f0.z; s0.w += f0.w;
                    s1.x += f1.x; s1.y += f1.y; s1.z += f1.z; s1.w += f1.w;
                }
                #pragma unroll
                for (int n2 = 0; n2 < 2; n2++) {
                    int r = r0 + n2;
                    float sv[4];
                    uint2 mu;
                    if (n2 == 0) {
                        sv[0]=s0.x; sv[1]=s0.y; sv[2]=s0.z; sv[3]=s0.w;
                        mu.x = *reinterpret_cast<uint32_t*>(&m0a);
                        mu.y = *reinterpret_cast<uint32_t*>(&m0b);
                    } else {
                        sv[0]=s1.x; sv[1]=s1.y; sv[2]=s1.z; sv[3]=s1.w;
                        mu.x = *reinterpret_cast<uint32_t*>(&m1a);
                        mu.y = *reinterpret_cast<uint32_t*>(&m1b);
                    }
                    uint32_t sh[4], sl[4];
                    #pragma unroll
                    for (int q = 0; q < 4; q++) {
                        __nv_bfloat16 h1 = __float2bfloat16_rn(sv[q]);
                        sh[q] = (uint32_t)__bfloat16_as_ushort(h1);
                        sl[q] = (uint32_t)__bfloat16_as_ushort(__float2bfloat16_rn(sv[q] - __bfloat162float(h1)));
                    }
                    uint32_t rowoff = (uint32_t)(r * 128) + (cb ^ (uint32_t)((r & 7) << 4));
                    uint2 u;
                    u.x = sh[0] | (sh[1] << 16); u.y = sh[2] | (sh[3] << 16);
                    *(uint2*)((char*)smem + (abase_hi - sb) + csum + rowoff) = u;
                    u.x = sl[0] | (sl[1] << 16); u.y = sl[2] | (sl[3] << 16);
                    *(uint2*)((char*)smem + (abase_lo - sb) + csum + rowoff) = u;
                    *(uint2*)((char*)smem + (abase_hi - sb) + cmax + rowoff) = mu;
                    // max lo residual == 0: no store; consumer skips it
                }
            }
            BAR_ARRIVE(1 + buf, THREADS);
        }
    } else {
        // ===================== CONSUMER (warps 16-19) =====================
        int ctid = tid - 512;           // 0..127
        int warp_n = wid - 16;          // 0..3, N=32 slice each; M=32 full
        int nlo = xin32 ? 4 : 2;        // chunks with nonzero A-lo
        // stage B (hi+lo = 128KB) with consumer threads only
        const __nv_bfloat16* Bh = g_bhi + (size_t)l * UU * K2;
        const __nv_bfloat16* Bl = g_blo + (size_t)l * UU * K2;
        #pragma unroll
        for (int t = 0; t < 64; t++) {
            int q = ctid + t * 128;     // 0..8191
            int arr = q >> 12;
            int rem = q & 4095;
            int ch = rem >> 10;
            int seg = rem & 1023;
            int row = seg >> 3, sgi = seg & 7;
            uint32_t dst = sb + (arr ? SB_LO : SB_HI) + ch * 16384 + SWZ((uint32_t)(row * 128 + sgi * 16));
            const char* src = (const char*)(arr ? Bl : Bh) + (size_t)row * 512 + ch * 128 + sgi * 16;
            cp16(dst, src);
        }
        asm volatile("cp.async.commit_group;" ::: "memory");
        float* sepi = (float*)(smem + S_EPI);
        if (ctid < 128) {
            sepi[ctid]       = __ldg(bias + ctid);
            sepi[128 + ctid] = g_bn_a[l * UU + ctid];
            sepi[256 + ctid] = g_bn_d[l * UU + ctid];
        }
        asm volatile("cp.async.wait_group 0;" ::: "memory");
        BAR_SYNC(5, 128);   // consumer-only: B + epi visible to all consumer warps

        uint32_t kaA = (uint32_t)((lane >> 4) * 16);
        uint32_t a_off[2], a_xor[2];
        #pragma unroll
        for (int i = 0; i < 2; i++) {
            int r = i * 16 + (lane & 15);
            a_off[i] = (uint32_t)(r * 128);
            a_xor[i] = (a_off[i] >> 3) & 0x70;
        }
        int lnB = (lane & 7) + ((lane >> 4) << 3);
        uint32_t kaB = (uint32_t)(((lane >> 3) & 1) * 16);
        uint32_t b_off[2], b_xor[2];
        #pragma unroll
        for (int p = 0; p < 2; p++) {
            int n = warp_n * 32 + p * 16 + lnB;
            b_off[p] = (uint32_t)(n * 128);
            b_xor[p] = (b_off[p] >> 3) & 0x70;
        }

        int it = 0;
        for (int tile = blockIdx.x; tile < NTILES; tile += GRIDSZ, it++) {
            int buf = it & 1;
            BAR_SYNC(1 + buf, THREADS);
            uint32_t abase_hi = sb + SA_BASE + buf * SA_BUFSZ;
            uint32_t abase_lo = abase_hi + 16384;

            float acc[2][4][4];
            #pragma unroll
            for (int i = 0; i < 2; i++)
                #pragma unroll
                for (int j = 0; j < 4; j++)
                    #pragma unroll
                    for (int q = 0; q < 4; q++) acc[i][j][q] = 0.f;

            #pragma unroll
            for (int ch = 0; ch < 4; ch++) {
                bool has_lo = (ch < nlo);
                uint32_t Ah  = abase_hi + ch * 4096;
                uint32_t Al  = abase_lo + ch * 4096;
                uint32_t Bhs = sb + SB_HI + ch * 16384;
                uint32_t Bls = sb + SB_LO + ch * 16384;
                #pragma unroll
                for (int ks = 0; ks < 4; ks++) {
                    uint32_t kb = (uint32_t)(ks * 32);
                    uint32_t ahi[2][4], alo[2][4], bhi[2][4], blo[2][4];
                    #pragma unroll
                    for (int i = 0; i < 2; i++) {
                        ldmx4(ahi[i], Ah + a_off[i] + ((kb + kaA) ^ a_xor[i]));
                        if (has_lo)
                            ldmx4(alo[i], Al + a_off[i] + ((kb + kaA) ^ a_xor[i]));
                    }
                    #pragma unroll
                    for (int p = 0; p < 2; p++) {
                        ldmx4(bhi[p], Bhs + b_off[p] + ((kb + kaB) ^ b_xor[p]));
                        ldmx4(blo[p], Bls + b_off[p] + ((kb + kaB) ^ b_xor[p]));
                    }
                    #pragma unroll
                    for (int i = 0; i < 2; i++)
                        #pragma unroll
                        for (int j = 0; j < 4; j++) {
                            int p = j >> 1, s2 = (j & 1) * 2;
                            mma_bf16(acc[i][j], ahi[i], bhi[p][s2], bhi[p][s2 + 1]);
                            mma_bf16(acc[i][j], ahi[i], blo[p][s2], blo[p][s2 + 1]);
                            if (has_lo)
                                mma_bf16(acc[i][j], alo[i], bhi[p][s2], bhi[p][s2 + 1]);
                        }
                }
            }
            BAR_ARRIVE(3 + buf, THREADS);   // A buffer free; epilogue runs after

            // ---- epilogue (outside the buffer critical section) ----
            int node0 = tile * TILE_M;
            if (!fuse_readout) {
                int mbase = node0 + (lane >> 2);
                #pragma unroll
                for (int i = 0; i < 2; i++)
                    #pragma unroll
                    for (int j = 0; j < 4; j++) {
                        int col = warp_n * 32 + j * 8 + (lane & 3) * 2;
                        float b0 = sepi[col], b1 = sepi[col + 1];
                        float a0 = sepi[128 + col], a1 = sepi[128 + col + 1];
                        float d0 = sepi[256 + col], d1 = sepi[256 + col + 1];
                        int r0 = mbase + i * 16;
                        float o0 = fmaxf(acc[i][j][0] + b0, 0.f) * a0 + d0;
                        float o1 = fmaxf(acc[i][j][1] + b1, 0.f) * a1 + d1;
                        *(__nv_bfloat162*)&xout[(size_t)r0 * UU + col] = __floats2bfloat162_rn(o0, o1);
                        o0 = fmaxf(acc[i][j][2] + b0, 0.f) * a0 + d0;
                        o1 = fmaxf(acc[i][j][3] + b1, 0.f) * a1 + d1;
                        *(__nv_bfloat162*)&xout[(size_t)(r0 + 8) * UU + col] = __floats2bfloat162_rn(o0, o1);
                    }
            } else {
                // final layer: column-reduce post-BN values (fp32) and atomicAdd to g_gm
                int b = node0 >> 12;
                float cs0[4], cs1[4];
                #pragma unroll
                for (int j = 0; j < 4; j++) { cs0[j] = 0.f; cs1[j] = 0.f; }
                #pragma unroll
                for (int i = 0; i < 2; i++)
                    #pragma unroll
                    for (int j = 0; j < 4; j++) {
                        int col = warp_n * 32 + j * 8 + (lane & 3) * 2;
                        float b0 = sepi[col], b1 = sepi[col + 1];
                        float a0 = sepi[128 + col], a1 = sepi[128 + col + 1];
                        float d0 = sepi[256 + col], d1 = sepi[256 + col + 1];
                        cs0[j] += fmaxf(acc[i][j][0] + b0, 0.f) * a0 + d0
                                + fmaxf(acc[i][j][2] + b0, 0.f) * a0 + d0;
                        cs1[j] += fmaxf(acc[i][j][1] + b1, 0.f) * a1 + d1
                                + fmaxf(acc[i][j][3] + b1, 0.f) * a1 + d1;
                    }
                #pragma unroll
                for (int j = 0; j < 4; j++) {
                    #pragma unroll
                    for (int e = 4; e < 32; e <<= 1) {
                        cs0[j] += __shfl_xor_sync(0xffffffffu, cs0[j], e);
                        cs1[j] += __shfl_xor_sync(0xffffffffu, cs1[j], e);
                    }
                }
                if (lane < 4) {
                    #pragma unroll
                    for (int j = 0; j < 4; j++) {
                        int col = warp_n * 32 + j * 8 + lane * 2;
                        atomicAdd(&g_gm[b * UU + col],     cs0[j] * (1.f / NN));
                        atomicAdd(&g_gm[b * UU + col + 1], cs1[j] * (1.f / NN));
                    }
                }
            }
        }
    }
}

// ------------------- fused projection MLP (relu(relu(g@Wp1+bp1)@Wp2+bp2)) -------------------
__global__ void mlp_kernel(const float* __restrict__ Wp1, const float* __restrict__ bp1,
                           const float* __restrict__ Wp2, const float* __restrict__ bp2,
                           float* __restrict__ out) {
    __shared__ float gs[UU];
    __shared__ float hs[UU];
    int b = blockIdx.x, j = threadIdx.x;   // 128 threads
    gs[j] = g_gm[b * UU + j];
    __syncthreads();
    float acc = bp1[j];
    #pragma unroll 8
    for (int k = 0; k < UU; k++) acc += gs[k] * Wp1[k * UU + j];
    hs[j] = fmaxf(acc, 0.f);
    __syncthreads();
    if (j < 64) {
        float a2 = bp2[j];
        #pragma unroll 8
        for (int k = 0; k < UU; k++) a2 += hs[k] * Wp2[k * 64 + j];
        out[b * 64 + j] = fmaxf(a2, 0.f);
    }
}

// ------------------- launch -------------------
extern "C" void kernel_launch(void* const* d_in, const int* in_sizes, int n_in,
                              void* d_out, int out_size) {
    const float* x0    = (const float*)d_in[0];
    const int*   ei    = (const int*)d_in[1];
    const float* W     = (const float*)d_in[2];
    const float* bvec  = (const float*)d_in[3];
    const float* gamma = (const float*)d_in[4];
    const float* beta  = (const float*)d_in[5];
    const float* mmean = (const float*)d_in[6];
    const float* mvar  = (const float*)d_in[7];
    const float* Wp1   = (const float*)d_in[8];
    const float* bp1   = (const float*)d_in[9];
    const float* Wp2   = (const float*)d_in[10];
    const float* bp2   = (const float*)d_in[11];

    cudaFuncSetAttribute(fused_layer_kernel, cudaFuncAttributeMaxDynamicSharedMemorySize, FUSED_SMEM);

    prep_kernel<<<96, 1024>>>(W, gamma, beta, mmean, mvar);

    __nv_bfloat16 *xa, *xb;
    cudaGetSymbolAddress((void**)&xa, g_xa);
    cudaGetSymbolAddress((void**)&xb, g_xb);

    // l0: fp32 x0 -> bf16 xa,  l1: xa -> xb,  l2: xb -> (fused readout into g_gm)
    fused_layer_kernel<<<GRIDSZ, THREADS, FUSED_SMEM>>>(
        0, x0, (const __nv_bfloat16*)nullptr, xa, ei, bvec + 0 * UU, 0);
    fused_layer_kernel<<<GRIDSZ, THREADS, FUSED_SMEM>>>(
        1, (const float*)nullptr, xa, xb, ei, bvec + 1 * UU, 0);
    fused_layer_kernel<<<GRIDSZ, THREADS, FUSED_SMEM>>>(
        2, (const float*)nullptr, xb, xa, ei, bvec + 2 * UU, 1);

    mlp_kernel<<<BB, 128>>>(Wp1, bp1, Wp2, bp2, (float*)d_out);
}

// round 16
// speedup vs baseline: 1.8277x; 1.1081x over previous
#include <cuda_runtime.h>
#include <cuda_bf16.h>
#include <math.h>
#include <stdint.h>

#define BB 8
#define NN 4096
#define DEG 16
#define UU 128
#define EE (NN*DEG)
#define MM (BB*NN)
#define K2 256
#define DEPTH 3
#define SCALE_C 1.2304489f
#define THREADS 640
#define TILE_M 32
#define NTILES (MM/TILE_M)
#define GRIDSZ 148

// ------------------- device scratch -------------------
__device__ __nv_bfloat16 g_xc[(size_t)MM * UU];        // bf16 copy of layer-0 input
__device__ __nv_bfloat16 g_xa[(size_t)MM * UU];
__device__ __nv_bfloat16 g_xb[(size_t)MM * UU];
__device__ __nv_bfloat16 g_bhi[DEPTH * UU * K2];       // folded W, [n][k] K-major, hi
__device__ __nv_bfloat16 g_blo[DEPTH * UU * K2];
__device__ float g_bn_a[DEPTH * UU];
__device__ float g_bn_d[DEPTH * UU];
__device__ float g_gm[BB * UU];

// ------------------- helpers -------------------
__device__ __forceinline__ uint32_t smem_u32(const void* p) {
    uint32_t a;
    asm("{ .reg .u64 t; cvta.to.shared.u64 t, %1; cvt.u32.u64 %0, t; }" : "=r"(a) : "l"(p));
    return a;
}
__device__ __forceinline__ void cp16(uint32_t dst, const void* src) {
    asm volatile("cp.async.cg.shared.global [%0], [%1], 16;" :: "r"(dst), "l"(src) : "memory");
}
__device__ __forceinline__ void ldmx4(uint32_t* r, uint32_t addr) {
    asm volatile("ldmatrix.sync.aligned.m8n8.x4.shared.b16 {%0,%1,%2,%3}, [%4];"
                 : "=r"(r[0]), "=r"(r[1]), "=r"(r[2]), "=r"(r[3]) : "r"(addr));
}
__device__ __forceinline__ void mma_bf16(float* c, const uint32_t* a, uint32_t b0, uint32_t b1) {
    asm volatile("mma.sync.aligned.m16n8k16.row.col.f32.bf16.bf16.f32 "
                 "{%0,%1,%2,%3}, {%4,%5,%6,%7}, {%8,%9}, {%0,%1,%2,%3};"
                 : "+f"(c[0]), "+f"(c[1]), "+f"(c[2]), "+f"(c[3])
                 : "r"(a[0]), "r"(a[1]), "r"(a[2]), "r"(a[3]), "r"(b0), "r"(b1));
}
__device__ __forceinline__ float4 bf4_to_f4(uint2 u) {
    __nv_bfloat162 p0 = *reinterpret_cast<__nv_bfloat162*>(&u.x);
    __nv_bfloat162 p1 = *reinterpret_cast<__nv_bfloat162*>(&u.y);
    float2 f0 = __bfloat1622float2(p0);
    float2 f1 = __bfloat1622float2(p1);
    return make_float4(f0.x, f0.y, f1.x, f1.y);
}
#define SWZ(off) ((off) ^ (((off) >> 3) & 0x70))
#define BAR_SYNC(id, cnt)   asm volatile("bar.sync %0, %1;"   :: "r"(id), "r"(cnt) : "memory")
#define BAR_ARRIVE(id, cnt) asm volatile("bar.arrive %0, %1;" :: "r"(id), "r"(cnt) : "memory")

// ------------------- x0 fp32 -> bf16 -------------------
__global__ void convert_kernel(const float* __restrict__ x0) {
    size_t i = (size_t)blockIdx.x * blockDim.x + threadIdx.x;   // one float4 each
    float4 v = __ldg((const float4*)(x0 + 4 * i));
    uint2 u;
    uint32_t a = (uint32_t)__bfloat16_as_ushort(__float2bfloat16_rn(v.x));
    uint32_t b = (uint32_t)__bfloat16_as_ushort(__float2bfloat16_rn(v.y));
    uint32_t c = (uint32_t)__bfloat16_as_ushort(__float2bfloat16_rn(v.z));
    uint32_t d = (uint32_t)__bfloat16_as_ushort(__float2bfloat16_rn(v.w));
    u.x = a | (b << 16);
    u.y = c | (d << 16);
    *(uint2*)(g_xc + 4 * i) = u;
}

// ------------------- prep: weight folding + BN fold + g_gm zero -------------------
__global__ void prep_kernel(const float* __restrict__ W,
                            const float* __restrict__ gamma, const float* __restrict__ beta,
                            const float* __restrict__ mm, const float* __restrict__ mv) {
    int t = blockIdx.x * blockDim.x + threadIdx.x;
    if (t < BB * UU) g_gm[t] = 0.f;
    if (t < DEPTH * UU) {
        float a = gamma[t] * rsqrtf(mv[t] + 1e-3f);
        g_bn_a[t] = a;
        g_bn_d[t] = beta[t] - mm[t] * a;
    }
    if (t >= DEPTH * K2 * UU) return;
    int j = t & 127;
    int k = (t >> 7) & 255;
    int l = t >> 15;
    const float c = SCALE_C;
    const float* Wl = W + (size_t)l * 1152 * UU;
    float v;
    if (k < 128) {
        float w0 = Wl[(0 * 128 + k) * UU + j];
        float w1 = Wl[(1 * 128 + k) * UU + j];
        float w2 = Wl[(2 * 128 + k) * UU + j];
        float w6 = Wl[(6 * 128 + k) * UU + j];
        float w7 = Wl[(7 * 128 + k) * UU + j];
        float w8 = Wl[(8 * 128 + k) * UU + j];
        v = (w0 + c * (w1 + w2)) * 0.0625f + w6 + c * (w7 + w8);
    } else {
        int kk = k - 128;
        float w3 = Wl[(3 * 128 + kk) * UU + j];
        float w4 = Wl[(4 * 128 + kk) * UU + j];
        float w5 = Wl[(5 * 128 + kk) * UU + j];
        v = w3 + c * (w4 + w5);
    }
    __nv_bfloat16 hi = __float2bfloat16_rn(v);
    size_t o = (size_t)l * UU * K2 + (size_t)j * K2 + k;
    g_bhi[o] = hi;
    g_blo[o] = __float2bfloat16_rn(v - __bfloat162float(hi));
}

// ------------------- warp-specialized fused layer kernel (bf16 everywhere) -------------------
// 640 threads: warps 0-15 produce (gather->A smem, 2 nodes each, depth-4 prefetch),
// warps 16-19 consume (MMA M=32 x N=32 slice each + epilogue).
// A = plain bf16 [ssum_hi | smax] (no A-lo): 16KB per buffer, double-buffered.
// B hi/lo resident (128KB). D = A*(Bhi+Blo) with fp32 accumulation.
#define SB_HI   0
#define SB_LO   65536
#define SA_BASE 131072
#define SA_BUFSZ 16384
#define S_EPI   (131072 + 2*SA_BUFSZ)
#define FUSED_SMEM (S_EPI + 3*128*4)
// named barriers: full[buf]=1+buf, empty[buf]=3+buf, consumer-init=5

__global__ __launch_bounds__(THREADS, 1) void fused_layer_kernel(
        int l, const __nv_bfloat16* __restrict__ xin, __nv_bfloat16* __restrict__ xout,
        const int* __restrict__ ei, const float* __restrict__ bias,
        int fuse_readout) {
    extern __shared__ __align__(1024) char smem[];
    uint32_t sb = smem_u32(smem);
    int tid = threadIdx.x, lane = tid & 31, wid = tid >> 5;

    if (wid < 16) {
        // ===================== PRODUCER (16 warps, 2 nodes each) =====================
        uint32_t csum = (uint32_t)(lane >> 4) * 4096;       // ssum chunk (0 or 1)
        uint32_t cmax = csum + 2 * 4096;                    // smax chunk (2 or 3)
        uint32_t cb   = (uint32_t)(lane & 15) * 8;
        int r0 = wid * 2;

        int it = 0;
        for (int tile = blockIdx.x; tile < NTILES; tile += GRIDSZ, it++) {
            int buf = it & 1;
            if (it >= 2) BAR_SYNC(3 + buf, THREADS);
            uint32_t abase = sb + SA_BASE + buf * SA_BUFSZ;

            int node0 = tile * TILE_M;
            int b = node0 >> 12;
            int nd0 = node0 & (NN - 1);
            const int* ep = ei + 2 * ((size_t)b * EE + (size_t)(nd0 + r0) * DEG);

            int myd0 = (lane < DEG) ? ep[2 * lane + 1] : 0;
            int myd1 = (lane < DEG) ? ep[2 * DEG + 2 * lane + 1] : 0;

            const __nv_bfloat16* xh = xin + (size_t)b * NN * UU;
            float4 s0 = make_float4(0.f, 0.f, 0.f, 0.f);
            float4 s1 = make_float4(0.f, 0.f, 0.f, 0.f);
            __nv_bfloat162 m0a, m0b, m1a, m1b;
            {
                uint32_t ni = 0xFF80FF80u;   // packed bf16 -inf
                m0a = *reinterpret_cast<__nv_bfloat162*>(&ni);
                m0b = m0a; m1a = m0a; m1b = m0a;
            }
            uint2 pf[4][2];
            #pragma unroll
            for (int pe = 0; pe < 4; pe++) {
                int d0 = __shfl_sync(0xffffffffu, myd0, pe);
                int d1 = __shfl_sync(0xffffffffu, myd1, pe);
                pf[pe][0] = __ldg((const uint2*)(xh + (size_t)d0 * UU + lane * 4));
                pf[pe][1] = __ldg((const uint2*)(xh + (size_t)d1 * UU + lane * 4));
            }
            #pragma unroll
            for (int e = 0; e < DEG; e++) {
                int slot = e & 3;
                uint2 v0 = pf[slot][0];
                uint2 v1 = pf[slot][1];
                if (e + 4 < DEG) {
                    int d0 = __shfl_sync(0xffffffffu, myd0, e + 4);
                    int d1 = __shfl_sync(0xffffffffu, myd1, e + 4);
                    pf[slot][0] = __ldg((const uint2*)(xh + (size_t)d0 * UU + lane * 4));
                    pf[slot][1] = __ldg((const uint2*)(xh + (size_t)d1 * UU + lane * 4));
                }
                m0a = __hmax2(m0a, *reinterpret_cast<__nv_bfloat162*>(&v0.x));
                m0b = __hmax2(m0b, *reinterpret_cast<__nv_bfloat162*>(&v0.y));
                m1a = __hmax2(m1a, *reinterpret_cast<__nv_bfloat162*>(&v1.x));
                m1b = __hmax2(m1b, *reinterpret_cast<__nv_bfloat162*>(&v1.y));
                float4 f0 = bf4_to_f4(v0);
                float4 f1 = bf4_to_f4(v1);
                s0.x += f0.x; s0.y += f0.y; s0.z += f0.z; s0.w += f0.w;
                s1.x += f1.x; s1.y += f1.y; s1.z += f1.z; s1.w += f1.w;
            }
            #pragma unroll
            for (int n2 = 0; n2 < 2; n2++) {
                int r = r0 + n2;
                float sv[4];
                uint2 mu;
                if (n2 == 0) {
                    sv[0]=s0.x; sv[1]=s0.y; sv[2]=s0.z; sv[3]=s0.w;
                    mu.x = *reinterpret_cast<uint32_t*>(&m0a);
                    mu.y = *reinterpret_cast<uint32_t*>(&m0b);
                } else {
                    sv[0]=s1.x; sv[1]=s1.y; sv[2]=s1.z; sv[3]=s1.w;
                    mu.x = *reinterpret_cast<uint32_t*>(&m1a);
                    mu.y = *reinterpret_cast<uint32_t*>(&m1b);
                }
                uint32_t sh[4];
                #pragma unroll
                for (int q = 0; q < 4; q++)
                    sh[q] = (uint32_t)__bfloat16_as_ushort(__float2bfloat16_rn(sv[q]));
                uint32_t rowoff = (uint32_t)(r * 128) + (cb ^ (uint32_t)((r & 7) << 4));
                uint2 u;
                u.x = sh[0] | (sh[1] << 16); u.y = sh[2] | (sh[3] << 16);
                *(uint2*)((char*)smem + (abase - sb) + csum + rowoff) = u;
                *(uint2*)((char*)smem + (abase - sb) + cmax + rowoff) = mu;
            }
            BAR_ARRIVE(1 + buf, THREADS);
        }
    } else {
        // ===================== CONSUMER (warps 16-19) =====================
        int ctid = tid - 512;           // 0..127
        int warp_n = wid - 16;          // 0..3
        const __nv_bfloat16* Bh = g_bhi + (size_t)l * UU * K2;
        const __nv_bfloat16* Bl = g_blo + (size_t)l * UU * K2;
        #pragma unroll
        for (int t = 0; t < 64; t++) {
            int q = ctid + t * 128;     // 0..8191
            int arr = q >> 12;
            int rem = q & 4095;
            int ch = rem >> 10;
            int seg = rem & 1023;
            int row = seg >> 3, sgi = seg & 7;
            uint32_t dst = sb + (arr ? SB_LO : SB_HI) + ch * 16384 + SWZ((uint32_t)(row * 128 + sgi * 16));
            const char* src = (const char*)(arr ? Bl : Bh) + (size_t)row * 512 + ch * 128 + sgi * 16;
            cp16(dst, src);
        }
        asm volatile("cp.async.commit_group;" ::: "memory");
        float* sepi = (float*)(smem + S_EPI);
        if (ctid < 128) {
            sepi[ctid]       = __ldg(bias + ctid);
            sepi[128 + ctid] = g_bn_a[l * UU + ctid];
            sepi[256 + ctid] = g_bn_d[l * UU + ctid];
        }
        asm volatile("cp.async.wait_group 0;" ::: "memory");
        BAR_SYNC(5, 128);

        uint32_t kaA = (uint32_t)((lane >> 4) * 16);
        uint32_t a_off[2], a_xor[2];
        #pragma unroll
        for (int i = 0; i < 2; i++) {
            int r = i * 16 + (lane & 15);
            a_off[i] = (uint32_t)(r * 128);
            a_xor[i] = (a_off[i] >> 3) & 0x70;
        }
        int lnB = (lane & 7) + ((lane >> 4) << 3);
        uint32_t kaB = (uint32_t)(((lane >> 3) & 1) * 16);
        uint32_t b_off[2], b_xor[2];
        #pragma unroll
        for (int p = 0; p < 2; p++) {
            int n = warp_n * 32 + p * 16 + lnB;
            b_off[p] = (uint32_t)(n * 128);
            b_xor[p] = (b_off[p] >> 3) & 0x70;
        }

        int it = 0;
        for (int tile = blockIdx.x; tile < NTILES; tile += GRIDSZ, it++) {
            int buf = it & 1;
            BAR_SYNC(1 + buf, THREADS);
            uint32_t abase = sb + SA_BASE + buf * SA_BUFSZ;

            float acc[2][4][4];
            #pragma unroll
            for (int i = 0; i < 2; i++)
                #pragma unroll
                for (int j = 0; j < 4; j++)
                    #pragma unroll
                    for (int q = 0; q < 4; q++) acc[i][j][q] = 0.f;

            #pragma unroll
            for (int ch = 0; ch < 4; ch++) {
                uint32_t Ah  = abase + ch * 4096;
                uint32_t Bhs = sb + SB_HI + ch * 16384;
                uint32_t Bls = sb + SB_LO + ch * 16384;
                #pragma unroll
                for (int ks = 0; ks < 4; ks++) {
                    uint32_t kb = (uint32_t)(ks * 32);
                    uint32_t ahi[2][4], bhi[2][4], blo[2][4];
                    #pragma unroll
                    for (int i = 0; i < 2; i++)
                        ldmx4(ahi[i], Ah + a_off[i] + ((kb + kaA) ^ a_xor[i]));
                    #pragma unroll
                    for (int p = 0; p < 2; p++) {
                        ldmx4(bhi[p], Bhs + b_off[p] + ((kb + kaB) ^ b_xor[p]));
                        ldmx4(blo[p], Bls + b_off[p] + ((kb + kaB) ^ b_xor[p]));
                    }
                    #pragma unroll
                    for (int i = 0; i < 2; i++)
                        #pragma unroll
                        for (int j = 0; j < 4; j++) {
                            int p = j >> 1, s2 = (j & 1) * 2;
                            mma_bf16(acc[i][j], ahi[i], bhi[p][s2], bhi[p][s2 + 1]);
                            mma_bf16(acc[i][j], ahi[i], blo[p][s2], blo[p][s2 + 1]);
                        }
                }
            }
            BAR_ARRIVE(3 + buf, THREADS);

            // ---- epilogue ----
            int node0 = tile * TILE_M;
            if (!fuse_readout) {
                int mbase = node0 + (lane >> 2);
                #pragma unroll
                for (int i = 0; i < 2; i++)
                    #pragma unroll
                    for (int j = 0; j < 4; j++) {
                        int col = warp_n * 32 + j * 8 + (lane & 3) * 2;
                        float b0 = sepi[col], b1 = sepi[col + 1];
                        float a0 = sepi[128 + col], a1 = sepi[128 + col + 1];
                        float d0 = sepi[256 + col], d1 = sepi[256 + col + 1];
                        int r0 = mbase + i * 16;
                        float o0 = fmaxf(acc[i][j][0] + b0, 0.f) * a0 + d0;
                        float o1 = fmaxf(acc[i][j][1] + b1, 0.f) * a1 + d1;
                        *(__nv_bfloat162*)&xout[(size_t)r0 * UU + col] = __floats2bfloat162_rn(o0, o1);
                        o0 = fmaxf(acc[i][j][2] + b0, 0.f) * a0 + d0;
                        o1 = fmaxf(acc[i][j][3] + b1, 0.f) * a1 + d1;
                        *(__nv_bfloat162*)&xout[(size_t)(r0 + 8) * UU + col] = __floats2bfloat162_rn(o0, o1);
                    }
            } else {
                int b = node0 >> 12;
                float cs0[4], cs1[4];
                #pragma unroll
                for (int j = 0; j < 4; j++) { cs0[j] = 0.f; cs1[j] = 0.f; }
                #pragma unroll
                for (int i = 0; i < 2; i++)
                    #pragma unroll
                    for (int j = 0; j < 4; j++) {
                        int col = warp_n * 32 + j * 8 + (lane & 3) * 2;
                        float b0 = sepi[col], b1 = sepi[col + 1];
                        float a0 = sepi[128 + col], a1 = sepi[128 + col + 1];
                        float d0 = sepi[256 + col], d1 = sepi[256 + col + 1];
                        cs0[j] += fmaxf(acc[i][j][0] + b0, 0.f) * a0 + d0
                                + fmaxf(acc[i][j][2] + b0, 0.f) * a0 + d0;
                        cs1[j] += fmaxf(acc[i][j][1] + b1, 0.f) * a1 + d1
                                + fmaxf(acc[i][j][3] + b1, 0.f) * a1 + d1;
                    }
                #pragma unroll
                for (int j = 0; j < 4; j++) {
                    #pragma unroll
                    for (int e = 4; e < 32; e <<= 1) {
                        cs0[j] += __shfl_xor_sync(0xffffffffu, cs0[j], e);
                        cs1[j] += __shfl_xor_sync(0xffffffffu, cs1[j], e);
                    }
                }
                if (lane < 4) {
                    #pragma unroll
                    for (int j = 0; j < 4; j++) {
                        int col = warp_n * 32 + j * 8 + lane * 2;
                        atomicAdd(&g_gm[b * UU + col],     cs0[j] * (1.f / NN));
                        atomicAdd(&g_gm[b * UU + col + 1], cs1[j] * (1.f / NN));
                    }
                }
            }
        }
    }
}

// ------------------- fused projection MLP -------------------
__global__ void mlp_kernel(const float* __restrict__ Wp1, const float* __restrict__ bp1,
                           const float* __restrict__ Wp2, const float* __restrict__ bp2,
                           float* __restrict__ out) {
    __shared__ float gs[UU];
    __shared__ float hs[UU];
    int b = blockIdx.x, j = threadIdx.x;
    gs[j] = g_gm[b * UU + j];
    __syncthreads();
    float acc = bp1[j];
    #pragma unroll 8
    for (int k = 0; k < UU; k++) acc += gs[k] * Wp1[k * UU + j];
    hs[j] = fmaxf(acc, 0.f);
    __syncthreads();
    if (j < 64) {
        float a2 = bp2[j];
        #pragma unroll 8
        for (int k = 0; k < UU; k++) a2 += hs[k] * Wp2[k * 64 + j];
        out[b * 64 + j] = fmaxf(a2, 0.f);
    }
}

// ------------------- launch -------------------
extern "C" void kernel_launch(void* const* d_in, const int* in_sizes, int n_in,
                              void* d_out, int out_size) {
    const float* x0    = (const float*)d_in[0];
    const int*   ei    = (const int*)d_in[1];
    const float* W     = (const float*)d_in[2];
    const float* bvec  = (const float*)d_in[3];
    const float* gamma = (const float*)d_in[4];
    const float* beta  = (const float*)d_in[5];
    const float* mmean = (const float*)d_in[6];
    const float* mvar  = (const float*)d_in[7];
    const float* Wp1   = (const float*)d_in[8];
    const float* bp1   = (const float*)d_in[9];
    const float* Wp2   = (const float*)d_in[10];
    const float* bp2   = (const float*)d_in[11];

    cudaFuncSetAttribute(fused_layer_kernel, cudaFuncAttributeMaxDynamicSharedMemorySize, FUSED_SMEM);

    prep_kernel<<<96, 1024>>>(W, gamma, beta, mmean, mvar);
    convert_kernel<<<(MM * UU / 4 + 255) / 256, 256>>>(x0);

    __nv_bfloat16 *xa, *xb, *xc;
    cudaGetSymbolAddress((void**)&xa, g_xa);
    cudaGetSymbolAddress((void**)&xb, g_xb);
    cudaGetSymbolAddress((void**)&xc, g_xc);

    // l0: xc -> xa,  l1: xa -> xb,  l2: xb -> (fused readout into g_gm)
    fused_layer_kernel<<<GRIDSZ, THREADS, FUSED_SMEM>>>(0, xc, xa, ei, bvec + 0 * UU, 0);
    fused_layer_kernel<<<GRIDSZ, THREADS, FUSED_SMEM>>>(1, xa, xb, ei, bvec + 1 * UU, 0);
    fused_layer_kernel<<<GRIDSZ, THREADS, FUSED_SMEM>>>(2, xb, xa, ei, bvec + 2 * UU, 1);

    mlp_kernel<<<BB, 128>>>(Wp1, bp1, Wp2, bp2, (float*)d_out);
}

// round 17
// speedup vs baseline: 1.8337x; 1.0033x over previous
#include <cuda_runtime.h>
#include <cuda_bf16.h>
#include <math.h>
#include <stdint.h>

#define BB 8
#define NN 4096
#define DEG 16
#define UU 128
#define EE (NN*DEG)
#define MM (BB*NN)
#define K2 256
#define DEPTH 3
#define SCALE_C 1.2304489f
#define THREADS 384
#define TILE_M 64
#define NTILES (MM/TILE_M)
#define GRIDSZ 128

// ------------------- device scratch -------------------
__device__ __nv_bfloat16 g_xc[(size_t)MM * UU];        // bf16 copy of layer-0 input
__device__ __nv_bfloat16 g_xa[(size_t)MM * UU];
__device__ __nv_bfloat16 g_xb[(size_t)MM * UU];
__device__ __nv_bfloat16 g_bhi[DEPTH * UU * K2];       // folded W, [n][k] K-major, hi
__device__ __nv_bfloat16 g_blo[DEPTH * UU * K2];
__device__ float g_bn_a[DEPTH * UU];
__device__ float g_bn_d[DEPTH * UU];
__device__ float g_gm[BB * UU];

// ------------------- helpers -------------------
__device__ __forceinline__ uint32_t smem_u32(const void* p) {
    uint32_t a;
    asm("{ .reg .u64 t; cvta.to.shared.u64 t, %1; cvt.u32.u64 %0, t; }" : "=r"(a) : "l"(p));
    return a;
}
__device__ __forceinline__ void cp16(uint32_t dst, const void* src) {
    asm volatile("cp.async.cg.shared.global [%0], [%1], 16;" :: "r"(dst), "l"(src) : "memory");
}
__device__ __forceinline__ void ldmx4(uint32_t* r, uint32_t addr) {
    asm volatile("ldmatrix.sync.aligned.m8n8.x4.shared.b16 {%0,%1,%2,%3}, [%4];"
                 : "=r"(r[0]), "=r"(r[1]), "=r"(r[2]), "=r"(r[3]) : "r"(addr));
}
__device__ __forceinline__ void mma_bf16(float* c, const uint32_t* a, uint32_t b0, uint32_t b1) {
    asm volatile("mma.sync.aligned.m16n8k16.row.col.f32.bf16.bf16.f32 "
                 "{%0,%1,%2,%3}, {%4,%5,%6,%7}, {%8,%9}, {%0,%1,%2,%3};"
                 : "+f"(c[0]), "+f"(c[1]), "+f"(c[2]), "+f"(c[3])
                 : "r"(a[0]), "r"(a[1]), "r"(a[2]), "r"(a[3]), "r"(b0), "r"(b1));
}
__device__ __forceinline__ float4 bf4_to_f4(uint2 u) {
    __nv_bfloat162 p0 = *reinterpret_cast<__nv_bfloat162*>(&u.x);
    __nv_bfloat162 p1 = *reinterpret_cast<__nv_bfloat162*>(&u.y);
    float2 f0 = __bfloat1622float2(p0);
    float2 f1 = __bfloat1622float2(p1);
    return make_float4(f0.x, f0.y, f1.x, f1.y);
}
#define SWZ(off) ((off) ^ (((off) >> 3) & 0x70))
#define BAR_SYNC(id, cnt)   asm volatile("bar.sync %0, %1;"   :: "r"(id), "r"(cnt) : "memory")
#define BAR_ARRIVE(id, cnt) asm volatile("bar.arrive %0, %1;" :: "r"(id), "r"(cnt) : "memory")

// ------------------- x0 fp32 -> bf16 -------------------
__global__ void convert_kernel(const float* __restrict__ x0) {
    size_t i = (size_t)blockIdx.x * blockDim.x + threadIdx.x;   // one float4 each
    float4 v = __ldg((const float4*)(x0 + 4 * i));
    uint2 u;
    uint32_t a = (uint32_t)__bfloat16_as_ushort(__float2bfloat16_rn(v.x));
    uint32_t b = (uint32_t)__bfloat16_as_ushort(__float2bfloat16_rn(v.y));
    uint32_t c = (uint32_t)__bfloat16_as_ushort(__float2bfloat16_rn(v.z));
    uint32_t d = (uint32_t)__bfloat16_as_ushort(__float2bfloat16_rn(v.w));
    u.x = a | (b << 16);
    u.y = c | (d << 16);
    *(uint2*)(g_xc + 4 * i) = u;
}

// ------------------- prep: weight folding + BN fold + g_gm zero -------------------
__global__ void prep_kernel(const float* __restrict__ W,
                            const float* __restrict__ gamma, const float* __restrict__ beta,
                            const float* __restrict__ mm, const float* __restrict__ mv) {
    int t = blockIdx.x * blockDim.x + threadIdx.x;
    if (t < BB * UU) g_gm[t] = 0.f;
    if (t < DEPTH * UU) {
        float a = gamma[t] * rsqrtf(mv[t] + 1e-3f);
        g_bn_a[t] = a;
        g_bn_d[t] = beta[t] - mm[t] * a;
    }
    if (t >= DEPTH * K2 * UU) return;
    int j = t & 127;
    int k = (t >> 7) & 255;
    int l = t >> 15;
    const float c = SCALE_C;
    const float* Wl = W + (size_t)l * 1152 * UU;
    float v;
    if (k < 128) {
        float w0 = Wl[(0 * 128 + k) * UU + j];
        float w1 = Wl[(1 * 128 + k) * UU + j];
        float w2 = Wl[(2 * 128 + k) * UU + j];
        float w6 = Wl[(6 * 128 + k) * UU + j];
        float w7 = Wl[(7 * 128 + k) * UU + j];
        float w8 = Wl[(8 * 128 + k) * UU + j];
        v = (w0 + c * (w1 + w2)) * 0.0625f + w6 + c * (w7 + w8);
    } else {
        int kk = k - 128;
        float w3 = Wl[(3 * 128 + kk) * UU + j];
        float w4 = Wl[(4 * 128 + kk) * UU + j];
        float w5 = Wl[(5 * 128 + kk) * UU + j];
        v = w3 + c * (w4 + w5);
    }
    __nv_bfloat16 hi = __float2bfloat16_rn(v);
    size_t o = (size_t)l * UU * K2 + (size_t)j * K2 + k;
    g_bhi[o] = hi;
    g_blo[o] = __float2bfloat16_rn(v - __bfloat162float(hi));
}

// ------------------- warp-specialized fused layer kernel -------------------
// 384 threads: warps 0-7 produce (gather->A smem, 8 nodes each: two 4-node
// interleaved groups with depth-4 prefetch), warps 8-11 consume
// (MMA M=64 full x N=32 slice each + epilogue).
// Tile M=64, N=128, K=256. A = plain bf16 [ssum_hi | smax], 32KB per buffer,
// double-buffered. B hi/lo resident (128KB). D = A*(Bhi+Blo), fp32 accum.
#define SB_HI   0
#define SB_LO   65536
#define SA_BASE 131072
#define SA_BUFSZ 32768
#define S_EPI   (131072 + 2*SA_BUFSZ)
#define FUSED_SMEM (S_EPI + 3*128*4)
// named barriers: full[buf]=1+buf, empty[buf]=3+buf, consumer-init=5

__global__ __launch_bounds__(THREADS, 1) void fused_layer_kernel(
        int l, const __nv_bfloat16* __restrict__ xin, __nv_bfloat16* __restrict__ xout,
        const int* __restrict__ ei, const float* __restrict__ bias,
        int fuse_readout) {
    extern __shared__ __align__(1024) char smem[];
    uint32_t sb = smem_u32(smem);
    int tid = threadIdx.x, lane = tid & 31, wid = tid >> 5;

    if (wid < 8) {
        // ===================== PRODUCER (8 warps, 8 nodes each) =====================
        uint32_t csum = (uint32_t)(lane >> 4) * 8192;       // ssum chunk (0 or 1)
        uint32_t cmax = csum + 2 * 8192;                    // smax chunk (2 or 3)
        uint32_t cb   = (uint32_t)(lane & 15) * 8;
        int r0 = wid * 8;

        int it = 0;
        for (int tile = blockIdx.x; tile < NTILES; tile += GRIDSZ, it++) {
            int buf = it & 1;
            if (it >= 2) BAR_SYNC(3 + buf, THREADS);
            uint32_t abase = sb + SA_BASE + buf * SA_BUFSZ;

            int node0 = tile * TILE_M;
            int b = node0 >> 12;
            int nd0 = node0 & (NN - 1);
            const __nv_bfloat16* xh = xin + (size_t)b * NN * UU;

            #pragma unroll
            for (int g = 0; g < 2; g++) {
                int rg = r0 + 4 * g;    // first of 4 nodes in this group
                const int* ep = ei + 2 * ((size_t)b * EE + (size_t)(nd0 + rg) * DEG);
                int myd[4];
                #pragma unroll
                for (int j = 0; j < 4; j++)
                    myd[j] = (lane < DEG) ? ep[j * 2 * DEG + 2 * lane + 1] : 0;

                float4 s[4];
                __nv_bfloat162 mA[4], mB[4];
                {
                    uint32_t ni = 0xFF80FF80u;   // packed bf16 -inf
                    __nv_bfloat162 nif = *reinterpret_cast<__nv_bfloat162*>(&ni);
                    #pragma unroll
                    for (int j = 0; j < 4; j++) {
                        s[j] = make_float4(0.f, 0.f, 0.f, 0.f);
                        mA[j] = nif; mB[j] = nif;
                    }
                }
                uint2 pf[4][4];   // slot x node
                #pragma unroll
                for (int pe = 0; pe < 4; pe++)
                    #pragma unroll
                    for (int j = 0; j < 4; j++) {
                        int d = __shfl_sync(0xffffffffu, myd[j], pe);
                        pf[pe][j] = __ldg((const uint2*)(xh + (size_t)d * UU + lane * 4));
                    }
                #pragma unroll
                for (int e = 0; e < DEG; e++) {
                    int slot = e & 3;
                    uint2 v[4];
                    #pragma unroll
                    for (int j = 0; j < 4; j++) v[j] = pf[slot][j];
                    if (e + 4 < DEG) {
                        #pragma unroll
                        for (int j = 0; j < 4; j++) {
                            int d = __shfl_sync(0xffffffffu, myd[j], e + 4);
                            pf[slot][j] = __ldg((const uint2*)(xh + (size_t)d * UU + lane * 4));
                        }
                    }
                    #pragma unroll
                    for (int j = 0; j < 4; j++) {
                        mA[j] = __hmax2(mA[j], *reinterpret_cast<__nv_bfloat162*>(&v[j].x));
                        mB[j] = __hmax2(mB[j], *reinterpret_cast<__nv_bfloat162*>(&v[j].y));
                        float4 f = bf4_to_f4(v[j]);
                        s[j].x += f.x; s[j].y += f.y; s[j].z += f.z; s[j].w += f.w;
                    }
                }
                #pragma unroll
                for (int j = 0; j < 4; j++) {
                    int r = rg + j;
                    uint32_t sh[4];
                    sh[0] = (uint32_t)__bfloat16_as_ushort(__float2bfloat16_rn(s[j].x));
                    sh[1] = (uint32_t)__bfloat16_as_ushort(__float2bfloat16_rn(s[j].y));
                    sh[2] = (uint32_t)__bfloat16_as_ushort(__float2bfloat16_rn(s[j].z));
                    sh[3] = (uint32_t)__bfloat16_as_ushort(__float2bfloat16_rn(s[j].w));
                    uint32_t rowoff = (uint32_t)(r * 128) + (cb ^ (uint32_t)((r & 7) << 4));
                    uint2 u;
                    u.x = sh[0] | (sh[1] << 16); u.y = sh[2] | (sh[3] << 16);
                    *(uint2*)((char*)smem + (abase - sb) + csum + rowoff) = u;
                    uint2 mu;
                    mu.x = *reinterpret_cast<uint32_t*>(&mA[j]);
                    mu.y = *reinterpret_cast<uint32_t*>(&mB[j]);
                    *(uint2*)((char*)smem + (abase - sb) + cmax + rowoff) = mu;
                }
            }
            BAR_ARRIVE(1 + buf, THREADS);
        }
    } else {
        // ===================== CONSUMER (warps 8-11, M=64 x N=32 each) =====================
        int ctid = tid - 256;           // 0..127
        int warp_n = wid - 8;           // 0..3
        const __nv_bfloat16* Bh = g_bhi + (size_t)l * UU * K2;
        const __nv_bfloat16* Bl = g_blo + (size_t)l * UU * K2;
        #pragma unroll
        for (int t = 0; t < 64; t++) {
            int q = ctid + t * 128;     // 0..8191
            int arr = q >> 12;
            int rem = q & 4095;
            int ch = rem >> 10;
            int seg = rem & 1023;
            int row = seg >> 3, sgi = seg & 7;
            uint32_t dst = sb + (arr ? SB_LO : SB_HI) + ch * 16384 + SWZ((uint32_t)(row * 128 + sgi * 16));
            const char* src = (const char*)(arr ? Bl : Bh) + (size_t)row * 512 + ch * 128 + sgi * 16;
            cp16(dst, src);
        }
        asm volatile("cp.async.commit_group;" ::: "memory");
        float* sepi = (float*)(smem + S_EPI);
        if (ctid < 128) {
            sepi[ctid]       = __ldg(bias + ctid);
            sepi[128 + ctid] = g_bn_a[l * UU + ctid];
            sepi[256 + ctid] = g_bn_d[l * UU + ctid];
        }
        asm volatile("cp.async.wait_group 0;" ::: "memory");
        BAR_SYNC(5, 128);

        uint32_t kaA = (uint32_t)((lane >> 4) * 16);
        uint32_t a_off[4], a_xor[4];
        #pragma unroll
        for (int i = 0; i < 4; i++) {
            int r = i * 16 + (lane & 15);
            a_off[i] = (uint32_t)(r * 128);
            a_xor[i] = (a_off[i] >> 3) & 0x70;
        }
        int lnB = (lane & 7) + ((lane >> 4) << 3);
        uint32_t kaB = (uint32_t)(((lane >> 3) & 1) * 16);
        uint32_t b_off[2], b_xor[2];
        #pragma unroll
        for (int p = 0; p < 2; p++) {
            int n = warp_n * 32 + p * 16 + lnB;
            b_off[p] = (uint32_t)(n * 128);
            b_xor[p] = (b_off[p] >> 3) & 0x70;
        }

        int it = 0;
        for (int tile = blockIdx.x; tile < NTILES; tile += GRIDSZ, it++) {
            int buf = it & 1;
            BAR_SYNC(1 + buf, THREADS);
            uint32_t abase = sb + SA_BASE + buf * SA_BUFSZ;

            float acc[4][4][4];
            #pragma unroll
            for (int i = 0; i < 4; i++)
                #pragma unroll
                for (int j = 0; j < 4; j++)
                    #pragma unroll
                    for (int q = 0; q < 4; q++) acc[i][j][q] = 0.f;

            #pragma unroll
            for (int ch = 0; ch < 4; ch++) {
                uint32_t Ah  = abase + ch * 8192;
                uint32_t Bhs = sb + SB_HI + ch * 16384;
                uint32_t Bls = sb + SB_LO + ch * 16384;
                #pragma unroll
                for (int ks = 0; ks < 4; ks++) {
                    uint32_t kb = (uint32_t)(ks * 32);
                    uint32_t bhi[2][4], blo[2][4];
                    #pragma unroll
                    for (int p = 0; p < 2; p++) {
                        ldmx4(bhi[p], Bhs + b_off[p] + ((kb + kaB) ^ b_xor[p]));
                        ldmx4(blo[p], Bls + b_off[p] + ((kb + kaB) ^ b_xor[p]));
                    }
                    #pragma unroll
                    for (int i = 0; i < 4; i++) {
                        uint32_t ahi[4];
                        ldmx4(ahi, Ah + a_off[i] + ((kb + kaA) ^ a_xor[i]));
                        #pragma unroll
                        for (int j = 0; j < 4; j++) {
                            int p = j >> 1, s2 = (j & 1) * 2;
                            mma_bf16(acc[i][j], ahi, bhi[p][s2], bhi[p][s2 + 1]);
                            mma_bf16(acc[i][j], ahi, blo[p][s2], blo[p][s2 + 1]);
                        }
                    }
                }
            }
            BAR_ARRIVE(3 + buf, THREADS);

            // ---- epilogue ----
            int node0 = tile * TILE_M;
            if (!fuse_readout) {
                int mbase = node0 + (lane >> 2);
                #pragma unroll
                for (int i = 0; i < 4; i++)
                    #pragma unroll
                    for (int j = 0; j < 4; j++) {
                        int col = warp_n * 32 + j * 8 + (lane & 3) * 2;
                        float b0 = sepi[col], b1 = sepi[col + 1];
                        float a0 = sepi[128 + col], a1 = sepi[128 + col + 1];
                        float d0 = sepi[256 + col], d1 = sepi[256 + col + 1];
                        int r0 = mbase + i * 16;
                        float o0 = fmaxf(acc[i][j][0] + b0, 0.f) * a0 + d0;
                        float o1 = fmaxf(acc[i][j][1] + b1, 0.f) * a1 + d1;
                        *(__nv_bfloat162*)&xout[(size_t)r0 * UU + col] = __floats2bfloat162_rn(o0, o1);
                        o0 = fmaxf(acc[i][j][2] + b0, 0.f) * a0 + d0;
                        o1 = fmaxf(acc[i][j][3] + b1, 0.f) * a1 + d1;
                        *(__nv_bfloat162*)&xout[(size_t)(r0 + 8) * UU + col] = __floats2bfloat162_rn(o0, o1);
                    }
            } else {
                int b = node0 >> 12;
                float cs0[4], cs1[4];
                #pragma unroll
                for (int j = 0; j < 4; j++) { cs0[j] = 0.f; cs1[j] = 0.f; }
                #pragma unroll
                for (int i = 0; i < 4; i++)
                    #pragma unroll
                    for (int j = 0; j < 4; j++) {
                        int col = warp_n * 32 + j * 8 + (lane & 3) * 2;
                        float b0 = sepi[col], b1 = sepi[col + 1];
                        float a0 = sepi[128 + col], a1 = sepi[128 + col + 1];
                        float d0 = sepi[256 + col], d1 = sepi[256 + col + 1];
                        cs0[j] += fmaxf(acc[i][j][0] + b0, 0.f) * a0 + d0
                                + fmaxf(acc[i][j][2] + b0, 0.f) * a0 + d0;
                        cs1[j] += fmaxf(acc[i][j][1] + b1, 0.f) * a1 + d1
                                + fmaxf(acc[i][j][3] + b1, 0.f) * a1 + d1;
                    }
                #pragma unroll
                for (int j = 0; j < 4; j++) {
                    #pragma unroll
                    for (int e = 4; e < 32; e <<= 1) {
                        cs0[j] += __shfl_xor_sync(0xffffffffu, cs0[j], e);
                        cs1[j] += __shfl_xor_sync(0xffffffffu, cs1[j], e);
                    }
                }
                if (lane < 4) {
                    #pragma unroll
                    for (int j = 0; j < 4; j++) {
                        int col = warp_n * 32 + j * 8 + lane * 2;
                        atomicAdd(&g_gm[b * UU + col],     cs0[j] * (1.f / NN));
                        atomicAdd(&g_gm[b * UU + col + 1], cs1[j] * (1.f / NN));
                    }
                }
            }
        }
    }
}

// ------------------- fused projection MLP -------------------
__global__ void mlp_kernel(const float* __restrict__ Wp1, const float* __restrict__ bp1,
                           const float* __restrict__ Wp2, const float* __restrict__ bp2,
                           float* __restrict__ out) {
    __shared__ float gs[UU];
    __shared__ float hs[UU];
    int b = blockIdx.x, j = threadIdx.x;
    gs[j] = g_gm[b * UU + j];
    __syncthreads();
    float acc = bp1[j];
    #pragma unroll 8
    for (int k = 0; k < UU; k++) acc += gs[k] * Wp1[k * UU + j];
    hs[j] = fmaxf(acc, 0.f);
    __syncthreads();
    if (j < 64) {
        float a2 = bp2[j];
        #pragma unroll 8
        for (int k = 0; k < UU; k++) a2 += hs[k] * Wp2[k * 64 + j];
        out[b * 64 + j] = fmaxf(a2, 0.f);
    }
}

// ------------------- launch -------------------
extern "C" void kernel_launch(void* const* d_in, const int* in_sizes, int n_in,
                              void* d_out, int out_size) {
    const float* x0    = (const float*)d_in[0];
    const int*   ei    = (const int*)d_in[1];
    const float* W     = (const float*)d_in[2];
    const float* bvec  = (const float*)d_in[3];
    const float* gamma = (const float*)d_in[4];
    const float* beta  = (const float*)d_in[5];
    const float* mmean = (const float*)d_in[6];
    const float* mvar  = (const float*)d_in[7];
    const float* Wp1   = (const float*)d_in[8];
    const float* bp1   = (const float*)d_in[9];
    const float* Wp2   = (const float*)d_in[10];
    const float* bp2   = (const float*)d_in[11];

    cudaFuncSetAttribute(fused_layer_kernel, cudaFuncAttributeMaxDynamicSharedMemorySize, FUSED_SMEM);

    prep_kernel<<<96, 1024>>>(W, gamma, beta, mmean, mvar);
    convert_kernel<<<(MM * UU / 4 + 255) / 256, 256>>>(x0);

    __nv_bfloat16 *xa, *xb, *xc;
    cudaGetSymbolAddress((void**)&xa, g_xa);
    cudaGetSymbolAddress((void**)&xb, g_xb);
    cudaGetSymbolAddress((void**)&xc, g_xc);

    // l0: xc -> xa,  l1: xa -> xb,  l2: xb -> (fused readout into g_gm)
    fused_layer_kernel<<<GRIDSZ, THREADS, FUSED_SMEM>>>(0, xc, xa, ei, bvec + 0 * UU, 0);
    fused_layer_kernel<<<GRIDSZ, THREADS, FUSED_SMEM>>>(1, xa, xb, ei, bvec + 1 * UU, 0);
    fused_layer_kernel<<<GRIDSZ, THREADS, FUSED_SMEM>>>(2, xb, xa, ei, bvec + 2 * UU, 1);

    mlp_kernel<<<BB, 128>>>(Wp1, bp1, Wp2, bp2, (float*)d_out);
}